// round 12
// baseline (speedup 1.0000x reference)
#include <cuda_runtime.h>
#include <cuda_bf16.h>

#define NN 50000
#define EE 800000
#define EPSB 1e-5f
#define SCAN_NBLK ((NN + 255) / 256)   // 196
#define H0 25088                        // 196 tiles of 128
#define H1R (NN - H0)                   // 24912

// ==================== device scratch ====================
__device__ __align__(256) unsigned int g_a1h[NN * 64], g_a1l[NN * 64];
__device__ __align__(256) unsigned int g_aggh[NN * 64], g_aggl[NN * 64];
__device__ __align__(256) unsigned int g_h1h[NN * 64], g_h1l[NN * 64];
__device__ __align__(256) unsigned int g_h2h[NN * 64], g_h2l[NN * 64];
__device__ __align__(256) unsigned int g_h3h[NN * 64], g_h3l[NN * 64];
__device__ __align__(256) unsigned int g_xh[NN * 32], g_xl[NN * 32];
__device__ __align__(256) int   g_cnt[3 * NN];
__device__ __align__(256) float g_invc[3 * NN];
__device__ __align__(256) int   g_rowptr[3 * (NN + 1)];
__device__ __align__(256) int   g_cursor[3 * NN];
__device__ __align__(256) int   g_partial[3 * SCAN_NBLK];
__device__ __align__(256) int2  g_col0e[EE];
__device__ __align__(256) int   g_col12[2 * EE];
__device__ __align__(256) unsigned short g_B1[128 * 256];
__device__ __align__(256) unsigned short g_B2[128 * 512];
__device__ __align__(256) unsigned short g_B3[128 * 512];
__device__ __align__(256) unsigned short g_B4[64 * 384];

// ==================== helpers ====================
__device__ __forceinline__ unsigned int smem_u32(const void* p) {
    unsigned int a;
    asm("{ .reg .u64 t; cvta.to.shared.u64 t, %1; cvt.u32.u64 %0, t; }" : "=r"(a) : "l"(p));
    return a;
}
__device__ __forceinline__ void cp_async16(unsigned int saddr, const void* gaddr) {
    asm volatile("cp.async.cg.shared.global [%0], [%1], 16;" :: "r"(saddr), "l"(gaddr));
}
__device__ __forceinline__ void ldsm_x4(unsigned int* r, unsigned int addr) {
    asm volatile("ldmatrix.sync.aligned.m8n8.x4.shared.b16 {%0,%1,%2,%3}, [%4];"
                 : "=r"(r[0]), "=r"(r[1]), "=r"(r[2]), "=r"(r[3]) : "r"(addr));
}
__device__ __forceinline__ void mma16816(float* d, const unsigned int* a,
                                         unsigned int b0, unsigned int b1) {
    asm volatile("mma.sync.aligned.m16n8k16.row.col.f32.bf16.bf16.f32 "
                 "{%0,%1,%2,%3}, {%4,%5,%6,%7}, {%8,%9}, {%0,%1,%2,%3};"
                 : "+f"(d[0]), "+f"(d[1]), "+f"(d[2]), "+f"(d[3])
                 : "r"(a[0]), "r"(a[1]), "r"(a[2]), "r"(a[3]), "r"(b0), "r"(b1));
}
__device__ __forceinline__ unsigned short f2b(float v) {
    return __bfloat16_as_ushort(__float2bfloat16(v));
}
__device__ __forceinline__ float b2f(unsigned short u) {
    return __bfloat162float(__ushort_as_bfloat16(u));
}
__device__ __forceinline__ void split2(float v0, float v1, unsigned int& ph, unsigned int& pl) {
    unsigned short h0 = f2b(v0), h1 = f2b(v1);
    unsigned short l0 = f2b(v0 - b2f(h0)), l1 = f2b(v1 - b2f(h1));
    ph = (unsigned int)h0 | ((unsigned int)h1 << 16);
    pl = (unsigned int)l0 | ((unsigned int)l1 << 16);
}
__device__ __forceinline__ float plo(unsigned int u) { return __uint_as_float(u << 16); }
__device__ __forceinline__ float phi(unsigned int u) { return __uint_as_float(u & 0xFFFF0000u); }

// ==================== prep helpers ====================
__device__ __forceinline__ void prepB_elem(const float* __restrict__ Wa, int Ka,
                                           const float* __restrict__ Wb, int Kb,
                                           int K, unsigned short* __restrict__ img, int idx) {
    int n = idx / K, k = idx - n * K;
    float w = 0.0f;
    if (k < Ka) w = Wa[n * Ka + k];
    else if (Wb != nullptr && (k - Ka) < Kb) w = Wb[n * Kb + (k - Ka)];
    unsigned short hb = f2b(w);
    unsigned short lb = f2b(w - b2f(hb));
    img[(size_t)n * 2 * K + k] = hb;
    img[(size_t)n * 2 * K + K + k] = lb;
}
#define SX (NN * 32)
#define SB1 (128 * 128)
#define SB2 (128 * 256)
#define SB3 (128 * 256)
#define SB4 (64 * 192)

__global__ void count0_prepB1(const int* __restrict__ e0, int* __restrict__ cnt,
                              const float* __restrict__ W1, unsigned short* __restrict__ B1) {
    int idx = blockIdx.x * blockDim.x + threadIdx.x;
    if (idx < EE) { atomicAdd(&cnt[e0[EE + idx]], 1); return; }
    idx -= EE;
    if (idx < SB1) prepB_elem(W1, 96, nullptr, 0, 128, B1, idx);
}
__global__ void count12_prep(const int* __restrict__ e1, const int* __restrict__ e2,
                             int* __restrict__ cnt,
                             const float* __restrict__ x,
                             unsigned int* __restrict__ xh, unsigned int* __restrict__ xl,
                             const float* __restrict__ Wl2, const float* __restrict__ Wr2,
                             const float* __restrict__ Wl3, const float* __restrict__ Wr3,
                             const float* __restrict__ W4,
                             unsigned short* __restrict__ B2, unsigned short* __restrict__ B3,
                             unsigned short* __restrict__ B4) {
    int idx = blockIdx.x * blockDim.x + threadIdx.x;
    if (idx < EE) { atomicAdd(&cnt[NN + e1[EE + idx]], 1); return; }
    if (idx < 2 * EE) { atomicAdd(&cnt[2 * NN + e2[EE + (idx - EE)]], 1); return; }
    idx -= 2 * EE;
    if (idx < SX) {
        int i = idx >> 5, j = idx & 31;
        float2 v = *(const float2*)(x + (size_t)i * 64 + 2 * j);
        unsigned int ph, pl;
        split2(v.x, v.y, ph, pl);
        xh[idx] = ph;
        xl[idx] = pl;
        return;
    }
    idx -= SX;
    if (idx < SB2) { prepB_elem(Wl2, 128, Wr2, 128, 256, B2, idx); return; }
    idx -= SB2;
    if (idx < SB3) { prepB_elem(Wl3, 128, Wr3, 128, 256, B3, idx); return; }
    idx -= SB3;
    if (idx < SB4) { prepB_elem(W4, 192, nullptr, 0, 192, B4, idx); }
}

// ==================== 3-phase scan ====================
__global__ void scanA(const int* __restrict__ cnt, int* __restrict__ partial, int Lbase) {
    int L = Lbase + blockIdx.y;
    int i = blockIdx.x * 256 + threadIdx.x;
    int v = (i < NN) ? cnt[L * NN + i] : 0;
#pragma unroll
    for (int o = 16; o; o >>= 1) v += __shfl_down_sync(0xFFFFFFFF, v, o);
    __shared__ int sw[8];
    if ((threadIdx.x & 31) == 0) sw[threadIdx.x >> 5] = v;
    __syncthreads();
    if (threadIdx.x < 8) {
        int s = sw[threadIdx.x];
#pragma unroll
        for (int o = 4; o; o >>= 1) s += __shfl_down_sync(0xFF, s, o);
        if (threadIdx.x == 0) partial[L * SCAN_NBLK + blockIdx.x] = s;
    }
}
__global__ void scanB(int* __restrict__ partial, int Lbase) {
    int L = Lbase + blockIdx.x;
    __shared__ int sh[256];
    int t = threadIdx.x;
    int v = (t < SCAN_NBLK) ? partial[L * SCAN_NBLK + t] : 0;
    sh[t] = v;
    __syncthreads();
#pragma unroll
    for (int o = 1; o < 256; o <<= 1) {
        int u = (t >= o) ? sh[t - o] : 0;
        __syncthreads();
        sh[t] += u;
        __syncthreads();
    }
    if (t < SCAN_NBLK) partial[L * SCAN_NBLK + t] = sh[t] - v;
}
__global__ void scanC(const int* __restrict__ cnt, const int* __restrict__ partial,
                      int* __restrict__ rowptr, int* __restrict__ cursor,
                      float* __restrict__ invc, int Lbase) {
    int L = Lbase + blockIdx.y;
    int t = threadIdx.x;
    int i = blockIdx.x * 256 + t;
    int c = (i < NN) ? cnt[L * NN + i] : 0;
    __shared__ int sh[256];
    sh[t] = c;
    __syncthreads();
#pragma unroll
    for (int o = 1; o < 256; o <<= 1) {
        int u = (t >= o) ? sh[t - o] : 0;
        __syncthreads();
        sh[t] += u;
        __syncthreads();
    }
    int ex = sh[t] - c + partial[L * SCAN_NBLK + blockIdx.x];
    if (i < NN) {
        rowptr[L * (NN + 1) + i] = ex;
        cursor[L * NN + i] = ex;
        invc[L * NN + i] = (c > 0) ? (1.0f / (float)c) : 0.0f;
    }
    if (i == 0) rowptr[L * (NN + 1) + NN] = EE;
}

// ==================== fill kernels ====================
__global__ void fill0(const int* __restrict__ e0, int* __restrict__ cursor,
                      int2* __restrict__ col0e) {
    int i = blockIdx.x * blockDim.x + threadIdx.x;
    if (i >= EE) return;
    int src = e0[i], dst = e0[EE + i];
    int pos = atomicAdd(&cursor[dst], 1);
    col0e[pos] = make_int2(src, i);
}
__global__ void fill12(const int* __restrict__ e1, const int* __restrict__ e2,
                       int* __restrict__ cursor, int* __restrict__ col12) {
    int i = blockIdx.x * blockDim.x + threadIdx.x;
    if (i < EE) {
        int src = e1[i], dst = e1[EE + i];
        int pos = atomicAdd(&cursor[NN + dst], 1);
        col12[pos] = src;
    } else if (i < 2 * EE) {
        int e = i - EE;
        int src = e2[e], dst = e2[EE + e];
        int pos = atomicAdd(&cursor[2 * NN + dst], 1);
        col12[EE + pos] = src;
    }
}

// ==================== aggregation (row-ranged) ====================
__global__ void agg1_kernel(const float* __restrict__ x, const float* __restrict__ ea,
                            const int* __restrict__ rowptr, const int2* __restrict__ ce,
                            const float* __restrict__ invc,
                            unsigned int* __restrict__ ah, unsigned int* __restrict__ al,
                            int rowBase, int rowEnd) {
    int warp = rowBase + ((blockIdx.x * blockDim.x + threadIdx.x) >> 5);
    int lane = threadIdx.x & 31;
    if (warp >= rowEnd) return;
    int s = rowptr[warp], e = rowptr[warp + 1];
    const float4* X4 = (const float4*)x;
    const float4* E4 = (const float4*)ea;
    const bool isx = lane < 16;
    const bool act = lane < 24;
    const int li = isx ? lane : (lane - 16);
    const float4* S = isx ? X4 : E4;
    float4 a = make_float4(0.f, 0.f, 0.f, 0.f);
    int p = s;
    for (; p + 4 <= e; p += 4) {
        int2 q0 = ce[p], q1 = ce[p + 1], q2 = ce[p + 2], q3 = ce[p + 3];
        if (act) {
            size_t b0 = isx ? ((size_t)q0.x * 16 + li) : ((size_t)q0.y * 8 + li);
            size_t b1 = isx ? ((size_t)q1.x * 16 + li) : ((size_t)q1.y * 8 + li);
            size_t b2 = isx ? ((size_t)q2.x * 16 + li) : ((size_t)q2.y * 8 + li);
            size_t b3 = isx ? ((size_t)q3.x * 16 + li) : ((size_t)q3.y * 8 + li);
            float4 v0 = S[b0], v1 = S[b1], v2 = S[b2], v3 = S[b3];
            a.x += (v0.x + v1.x) + (v2.x + v3.x);
            a.y += (v0.y + v1.y) + (v2.y + v3.y);
            a.z += (v0.z + v1.z) + (v2.z + v3.z);
            a.w += (v0.w + v1.w) + (v2.w + v3.w);
        }
    }
    for (; p < e; p++) {
        int2 q = ce[p];
        if (act) {
            size_t b = isx ? ((size_t)q.x * 16 + li) : ((size_t)q.y * 8 + li);
            float4 v = S[b];
            a.x += v.x; a.y += v.y; a.z += v.z; a.w += v.w;
        }
    }
    float ic = invc[warp];
    uint2 ph = make_uint2(0, 0), pl = make_uint2(0, 0);
    if (act) {
        split2(a.x * ic, a.y * ic, ph.x, pl.x);
        split2(a.z * ic, a.w * ic, ph.y, pl.y);
    }
    ((uint2*)ah)[(size_t)warp * 32 + lane] = ph;
    ((uint2*)al)[(size_t)warp * 32 + lane] = pl;
}

__global__ void aggH_kernel(const unsigned int* __restrict__ hh, const unsigned int* __restrict__ hl,
                            const int* __restrict__ rowptr, const int* __restrict__ col,
                            const float* __restrict__ invc,
                            unsigned int* __restrict__ oh, unsigned int* __restrict__ ol,
                            int rowBase, int rowEnd) {
    int warp = rowBase + ((blockIdx.x * blockDim.x + threadIdx.x) >> 5);
    int lane = threadIdx.x & 31;
    if (warp >= rowEnd) return;
    int s = rowptr[warp], e = rowptr[warp + 1];
    const uint4* S = (lane < 16) ? (const uint4*)hh : (const uint4*)hl;
    const int li = lane & 15;
    float a0 = 0.f, a1 = 0.f, a2 = 0.f, a3 = 0.f;
    float a4 = 0.f, a5 = 0.f, a6 = 0.f, a7 = 0.f;
    int p = s;
    for (; p + 4 <= e; p += 4) {
        int c0 = col[p], c1 = col[p + 1], c2 = col[p + 2], c3 = col[p + 3];
        uint4 v0 = S[(size_t)c0 * 16 + li];
        uint4 v1 = S[(size_t)c1 * 16 + li];
        uint4 v2 = S[(size_t)c2 * 16 + li];
        uint4 v3 = S[(size_t)c3 * 16 + li];
        a0 += (plo(v0.x) + plo(v1.x)) + (plo(v2.x) + plo(v3.x));
        a1 += (phi(v0.x) + phi(v1.x)) + (phi(v2.x) + phi(v3.x));
        a2 += (plo(v0.y) + plo(v1.y)) + (plo(v2.y) + plo(v3.y));
        a3 += (phi(v0.y) + phi(v1.y)) + (phi(v2.y) + phi(v3.y));
        a4 += (plo(v0.z) + plo(v1.z)) + (plo(v2.z) + plo(v3.z));
        a5 += (phi(v0.z) + phi(v1.z)) + (phi(v2.z) + phi(v3.z));
        a6 += (plo(v0.w) + plo(v1.w)) + (plo(v2.w) + plo(v3.w));
        a7 += (phi(v0.w) + phi(v1.w)) + (phi(v2.w) + phi(v3.w));
    }
    for (; p < e; p++) {
        uint4 v = S[(size_t)col[p] * 16 + li];
        a0 += plo(v.x); a1 += phi(v.x);
        a2 += plo(v.y); a3 += phi(v.y);
        a4 += plo(v.z); a5 += phi(v.z);
        a6 += plo(v.w); a7 += phi(v.w);
    }
    a0 += __shfl_down_sync(0xFFFFFFFF, a0, 16);
    a1 += __shfl_down_sync(0xFFFFFFFF, a1, 16);
    a2 += __shfl_down_sync(0xFFFFFFFF, a2, 16);
    a3 += __shfl_down_sync(0xFFFFFFFF, a3, 16);
    a4 += __shfl_down_sync(0xFFFFFFFF, a4, 16);
    a5 += __shfl_down_sync(0xFFFFFFFF, a5, 16);
    a6 += __shfl_down_sync(0xFFFFFFFF, a6, 16);
    a7 += __shfl_down_sync(0xFFFFFFFF, a7, 16);
    if (lane < 16) {
        float ic = invc[warp];
        uint4 ph, pl;
        split2(a0 * ic, a1 * ic, ph.x, pl.x);
        split2(a2 * ic, a3 * ic, ph.y, pl.y);
        split2(a4 * ic, a5 * ic, ph.z, pl.z);
        split2(a6 * ic, a7 * ic, ph.w, pl.w);
        ((uint4*)oh)[(size_t)warp * 16 + lane] = ph;
        ((uint4*)ol)[(size_t)warp * 16 + lane] = pl;
    }
}

// ==================== warp-MMA GEMM (row-ranged) ====================
template <int K0, int K1, int NCOL, int MODE>
__global__ __launch_bounds__(256, 2)
void gemm_mma(const unsigned short* __restrict__ A0h, const unsigned short* __restrict__ A0l,
              const unsigned short* __restrict__ A1h, const unsigned short* __restrict__ A1l,
              const unsigned short* __restrict__ Bp,
              const float* __restrict__ bias,
              const float* __restrict__ gamma, const float* __restrict__ beta,
              const float* __restrict__ mean, const float* __restrict__ var,
              const float* __restrict__ invc,
              unsigned int* __restrict__ outHi, unsigned int* __restrict__ outLo,
              const float* __restrict__ W5, const float* __restrict__ b5,
              float* __restrict__ finalOut, int rowBase) {
    constexpr int K = K0 + K1;
    constexpr int P = K / 64;
    constexpr int NCHUNK = 2 * P;
    constexpr int ABYTES = 128 * 128;
    constexpr int BBYTES = NCOL * 128;
    constexpr int STAGE = ABYTES + 2 * BBYTES;
    constexpr int WNC = NCOL / 2;
    constexpr int NI = WNC / 8;

    extern __shared__ char smem[];
    const unsigned int sbase = smem_u32(smem);

    const int tid = threadIdx.x;
    const int lane = tid & 31;
    const int warp = tid >> 5;
    const int wr = warp & 3;
    const int wc = warp >> 2;
    const int brow = rowBase + blockIdx.x * 128;

    const int lane16 = lane & 15;
    const int lhalf = lane >> 4;
    const int swz = lane16 & 7;

    float acc[2][NI][4];
#pragma unroll
    for (int mi = 0; mi < 2; mi++)
#pragma unroll
        for (int ni = 0; ni < NI; ni++)
#pragma unroll
            for (int q = 0; q < 4; q++) acc[mi][ni][q] = 0.0f;

    for (int cc = 0; cc <= NCHUNK; cc++) {
        if (cc < NCHUNK) {
            const int stage = cc & 1;
            const bool ph1 = cc < P;
            const int kk = (ph1 ? cc : cc - P) * 64;
            const unsigned short* A0 = ph1 ? A0h : A0l;
            const unsigned short* A1 = ph1 ? A1h : A1l;
            const unsigned int sA = sbase + stage * STAGE;
            const unsigned int sB0 = sA + ABYTES;
            const unsigned int sB1 = sB0 + BBYTES;
#pragma unroll
            for (int i = 0; i < 4; i++) {
                int idx = tid + i * 256;
                int r = idx >> 3, c = idx & 7;
                int rg = min(brow + r, NN - 1);
                int ke = kk + c * 8;
                const unsigned short* g =
                    (K1 == 0 || ke < K0) ? (A0 + (size_t)rg * K0 + ke)
                                         : (A1 + (size_t)rg * K1 + (ke - K0));
                cp_async16(sA + r * 128 + ((c ^ (r & 7)) << 4), g);
            }
#pragma unroll
            for (int i = 0; i < (NCOL * 8) / 256; i++) {
                int idx = tid + i * 256;
                int n = idx >> 3, c = idx & 7;
                cp_async16(sB0 + n * 128 + ((c ^ (n & 7)) << 4),
                           Bp + (size_t)n * (2 * K) + kk + c * 8);
            }
            if (ph1) {
#pragma unroll
                for (int i = 0; i < (NCOL * 8) / 256; i++) {
                    int idx = tid + i * 256;
                    int n = idx >> 3, c = idx & 7;
                    cp_async16(sB1 + n * 128 + ((c ^ (n & 7)) << 4),
                               Bp + (size_t)n * (2 * K) + K + kk + c * 8);
                }
            }
            asm volatile("cp.async.commit_group;");
        }
        if (cc == 0) continue;
        if (cc < NCHUNK) asm volatile("cp.async.wait_group 1;");
        else asm volatile("cp.async.wait_group 0;");
        __syncthreads();

        const int stage = (cc - 1) & 1;
        const bool ph = (cc - 1) < P;
        const unsigned int sA = sbase + stage * STAGE;
        const unsigned int sB0 = sA + ABYTES;
#pragma unroll
        for (int ks = 0; ks < 4; ks++) {
            const unsigned int coff = (unsigned int)((((ks << 1) | lhalf) ^ swz) << 4);
            unsigned int a[2][4];
#pragma unroll
            for (int mi = 0; mi < 2; mi++)
                ldsm_x4(a[mi], sA + (wr * 32 + mi * 16 + lane16) * 128 + coff);
#pragma unroll
            for (int h = 0; h < 2; h++) {
                if (h == 1 && !ph) break;
                const unsigned int sB = sB0 + h * BBYTES;
                unsigned int b[NI][2];
#pragma unroll
                for (int nb = 0; nb < NI / 2; nb++) {
                    unsigned int r4[4];
                    ldsm_x4(r4, sB + (wc * WNC + nb * 16 + lane16) * 128 + coff);
                    b[nb * 2][0] = r4[0];
                    b[nb * 2 + 1][0] = r4[1];
                    b[nb * 2][1] = r4[2];
                    b[nb * 2 + 1][1] = r4[3];
                }
#pragma unroll
                for (int mi = 0; mi < 2; mi++)
#pragma unroll
                    for (int ni = 0; ni < NI; ni++)
                        mma16816(acc[mi][ni], a[mi], b[ni][0], b[ni][1]);
            }
        }
        __syncthreads();
    }

    // ---- epilogue ----
    if (MODE == 2) {
        float* part = (float*)smem;
        const int g = lane >> 2, tg = lane & 3;
        float w5b = __ldg(b5);
#pragma unroll
        for (int mi = 0; mi < 2; mi++) {
            float p0 = 0.0f, p1 = 0.0f;
#pragma unroll
            for (int ni = 0; ni < NI; ni++) {
                int cb = wc * WNC + ni * 8 + tg * 2;
                float w0 = __ldg(W5 + cb), w1 = __ldg(W5 + cb + 1);
                float b0 = __ldg(bias + cb), b1 = __ldg(bias + cb + 1);
                p0 += fmaxf(acc[mi][ni][0] + b0, 0.0f) * w0 +
                      fmaxf(acc[mi][ni][1] + b1, 0.0f) * w1;
                p1 += fmaxf(acc[mi][ni][2] + b0, 0.0f) * w0 +
                      fmaxf(acc[mi][ni][3] + b1, 0.0f) * w1;
            }
            p0 += __shfl_xor_sync(0xFFFFFFFF, p0, 1);
            p0 += __shfl_xor_sync(0xFFFFFFFF, p0, 2);
            p1 += __shfl_xor_sync(0xFFFFFFFF, p1, 1);
            p1 += __shfl_xor_sync(0xFFFFFFFF, p1, 2);
            if (tg == 0) {
                part[(wr * 32 + mi * 16 + g) * 2 + wc] = p0;
                part[(wr * 32 + mi * 16 + 8 + g) * 2 + wc] = p1;
            }
        }
        __syncthreads();
        if (tid < 128) {
            int row = brow + tid;
            if (row < NN) finalOut[row] = part[tid * 2] + part[tid * 2 + 1] + w5b;
        }
        return;
    }

    float* sc = (float*)smem;
    float* sf = sc + NCOL;
    float* bi = sf + NCOL;
    if (tid < NCOL) {
        float s = gamma[tid] * rsqrtf(var[tid] + EPSB);
        sc[tid] = s;
        sf[tid] = beta[tid] - mean[tid] * s;
        bi[tid] = bias[tid];
    }
    __syncthreads();

    const int g = lane >> 2, tg = lane & 3;
#pragma unroll
    for (int mi = 0; mi < 2; mi++) {
        int row0 = brow + wr * 32 + mi * 16 + g;
        int row1 = row0 + 8;
        float msk0 = 1.0f, msk1 = 1.0f;
        if (MODE == 0) {
            msk0 = (row0 < NN && invc[row0] > 0.0f) ? 1.0f : 0.0f;
            msk1 = (row1 < NN && invc[row1] > 0.0f) ? 1.0f : 0.0f;
        }
#pragma unroll
        for (int ni = 0; ni < NI; ni++) {
            int cb = wc * WNC + ni * 8 + tg * 2;
            float s0 = sc[cb], s1 = sc[cb + 1];
            float f0 = sf[cb], f1 = sf[cb + 1];
            float b0 = bi[cb], b1 = bi[cb + 1];
            if (row0 < NN) {
                float v0 = acc[mi][ni][0] + b0, v1 = acc[mi][ni][1] + b1;
                if (MODE == 0) { v0 = fmaxf(v0, 0.f) * msk0; v1 = fmaxf(v1, 0.f) * msk0; }
                v0 = fmaxf(s0 * v0 + f0, 0.0f);
                v1 = fmaxf(s1 * v1 + f1, 0.0f);
                unsigned int ph, pl;
                split2(v0, v1, ph, pl);
                outHi[(size_t)row0 * 64 + (cb >> 1)] = ph;
                outLo[(size_t)row0 * 64 + (cb >> 1)] = pl;
            }
            if (row1 < NN) {
                float v0 = acc[mi][ni][2] + b0, v1 = acc[mi][ni][3] + b1;
                if (MODE == 0) { v0 = fmaxf(v0, 0.f) * msk1; v1 = fmaxf(v1, 0.f) * msk1; }
                v0 = fmaxf(s0 * v0 + f0, 0.0f);
                v1 = fmaxf(s1 * v1 + f1, 0.0f);
                unsigned int ph, pl;
                split2(v0, v1, ph, pl);
                outHi[(size_t)row1 * 64 + (cb >> 1)] = ph;
                outLo[(size_t)row1 * 64 + (cb >> 1)] = pl;
            }
        }
    }
}

// ==================== launch (agg/gemm half-split pipeline) ====================
extern "C" void kernel_launch(void* const* d_in, const int* in_sizes, int n_in,
                              void* d_out, int out_size) {
    const float* x   = (const float*)d_in[0];
    const int*   ei0 = (const int*)d_in[1];
    const int*   ei1 = (const int*)d_in[2];
    const int*   ei2 = (const int*)d_in[3];
    const float* ea  = (const float*)d_in[4];
    const float* W1  = (const float*)d_in[5];
    const float* b1  = (const float*)d_in[6];
    const float* g1  = (const float*)d_in[7];
    const float* be1 = (const float*)d_in[8];
    const float* m1  = (const float*)d_in[9];
    const float* v1  = (const float*)d_in[10];
    const float* Wl2 = (const float*)d_in[11];
    const float* bl2 = (const float*)d_in[12];
    const float* Wr2 = (const float*)d_in[13];
    const float* g2  = (const float*)d_in[14];
    const float* be2 = (const float*)d_in[15];
    const float* m2  = (const float*)d_in[16];
    const float* v2  = (const float*)d_in[17];
    const float* Wl3 = (const float*)d_in[18];
    const float* bl3 = (const float*)d_in[19];
    const float* Wr3 = (const float*)d_in[20];
    const float* g3  = (const float*)d_in[21];
    const float* be3 = (const float*)d_in[22];
    const float* m3  = (const float*)d_in[23];
    const float* v3  = (const float*)d_in[24];
    const float* W4  = (const float*)d_in[25];
    const float* b4  = (const float*)d_in[26];
    const float* W5  = (const float*)d_in[27];
    const float* b5  = (const float*)d_in[28];
    float* out = (float*)d_out;

    unsigned int *a1h, *a1l, *aggh, *aggl, *h1h, *h1l, *h2h, *h2l, *h3h, *h3l, *xh, *xl;
    float *invc;
    int *cnt, *rowptr, *cursor, *col12, *partial;
    int2* col0e;
    unsigned short *B1, *B2, *B3, *B4;
    cudaGetSymbolAddress((void**)&a1h, g_a1h);   cudaGetSymbolAddress((void**)&a1l, g_a1l);
    cudaGetSymbolAddress((void**)&aggh, g_aggh); cudaGetSymbolAddress((void**)&aggl, g_aggl);
    cudaGetSymbolAddress((void**)&h1h, g_h1h);   cudaGetSymbolAddress((void**)&h1l, g_h1l);
    cudaGetSymbolAddress((void**)&h2h, g_h2h);   cudaGetSymbolAddress((void**)&h2l, g_h2l);
    cudaGetSymbolAddress((void**)&h3h, g_h3h);   cudaGetSymbolAddress((void**)&h3l, g_h3l);
    cudaGetSymbolAddress((void**)&xh, g_xh);     cudaGetSymbolAddress((void**)&xl, g_xl);
    cudaGetSymbolAddress((void**)&cnt, g_cnt);
    cudaGetSymbolAddress((void**)&invc, g_invc);
    cudaGetSymbolAddress((void**)&rowptr, g_rowptr);
    cudaGetSymbolAddress((void**)&cursor, g_cursor);
    cudaGetSymbolAddress((void**)&partial, g_partial);
    cudaGetSymbolAddress((void**)&col0e, g_col0e);
    cudaGetSymbolAddress((void**)&col12, g_col12);
    cudaGetSymbolAddress((void**)&B1, g_B1);
    cudaGetSymbolAddress((void**)&B2, g_B2);
    cudaGetSymbolAddress((void**)&B3, g_B3);
    cudaGetSymbolAddress((void**)&B4, g_B4);

    const int SMC = 2 * (128 * 128 + 2 * 128 * 128);  // 98304
    const int SMM = 2 * (128 * 128 + 2 * 64 * 128);   // 65536
    cudaFuncSetAttribute(gemm_mma<128, 0, 128, 0>,
                         cudaFuncAttributeMaxDynamicSharedMemorySize, SMC);
    cudaFuncSetAttribute(gemm_mma<128, 128, 128, 1>,
                         cudaFuncAttributeMaxDynamicSharedMemorySize, SMC);
    cudaFuncSetAttribute(gemm_mma<128, 64, 64, 2>,
                         cudaFuncAttributeMaxDynamicSharedMemorySize, SMM);

    // one-time stream/event setup (resources only)
    static cudaStream_t s1 = nullptr;
    static cudaEvent_t ev[12];
    if (s1 == nullptr) {
        cudaStreamCreateWithFlags(&s1, cudaStreamNonBlocking);
        for (int i = 0; i < 12; i++) cudaEventCreateWithFlags(&ev[i], cudaEventDisableTiming);
    }

    // half grids
    const int AG0 = (H0 + 7) / 8, AG1 = (H1R + 7) / 8;
    const int GG0 = H0 / 128;                 // 196
    const int GG1 = (H1R + 127) / 128;        // 195
    dim3 scan0_grid(SCAN_NBLK, 1);
    dim3 scan12_grid(SCAN_NBLK, 2);

    // ---- root fork ----
    cudaMemsetAsync(cnt, 0, 3 * NN * sizeof(int), 0);
    cudaEventRecord(ev[0], 0);
    cudaStreamWaitEvent(s1, ev[0], 0);

    // ---- s1: lists 1,2 CSR + heavy prep ----
    count12_prep<<<(2 * EE + SX + SB2 + SB3 + SB4 + 255) / 256, 256, 0, s1>>>(
        ei1, ei2, cnt, x, xh, xl, Wl2, Wr2, Wl3, Wr3, W4, B2, B3, B4);
    scanA<<<scan12_grid, 256, 0, s1>>>(cnt, partial, 1);
    scanB<<<2, 256, 0, s1>>>(partial, 1);
    scanC<<<scan12_grid, 256, 0, s1>>>(cnt, partial, rowptr, cursor, invc, 1);
    fill12<<<(2 * EE + 255) / 256, 256, 0, s1>>>(ei1, ei2, cursor, col12);

    // ---- s0: list0 CSR ----
    count0_prepB1<<<(EE + SB1 + 255) / 256, 256>>>(ei0, cnt, W1, B1);
    scanA<<<scan0_grid, 256>>>(cnt, partial, 0);
    scanB<<<1, 256>>>(partial, 0);
    scanC<<<scan0_grid, 256>>>(cnt, partial, rowptr, cursor, invc, 0);
    fill0<<<(EE + 255) / 256, 256>>>(ei0, cursor, col0e);

    // ===== conv1: agg on s0, gemm on s1, half pipelined =====
    agg1_kernel<<<AG0, 256>>>(x, ea, rowptr, col0e, invc, a1h, a1l, 0, H0);
    cudaEventRecord(ev[1], 0);
    agg1_kernel<<<AG1, 256>>>(x, ea, rowptr, col0e, invc, a1h, a1l, H0, NN);
    cudaEventRecord(ev[2], 0);
    cudaStreamWaitEvent(s1, ev[1], 0);
    gemm_mma<128, 0, 128, 0><<<GG0, 256, SMC, s1>>>(
        (unsigned short*)a1h, (unsigned short*)a1l, (unsigned short*)a1h, (unsigned short*)a1l,
        B1, b1, g1, be1, m1, v1, invc, h1h, h1l, nullptr, nullptr, nullptr, 0);
    cudaStreamWaitEvent(s1, ev[2], 0);
    gemm_mma<128, 0, 128, 0><<<GG1, 256, SMC, s1>>>(
        (unsigned short*)a1h, (unsigned short*)a1l, (unsigned short*)a1h, (unsigned short*)a1l,
        B1, b1, g1, be1, m1, v1, invc, h1h, h1l, nullptr, nullptr, nullptr, H0);
    cudaEventRecord(ev[3], s1);

    // ===== conv2 =====
    cudaStreamWaitEvent(0, ev[3], 0);
    aggH_kernel<<<AG0, 256>>>(h1h, h1l, rowptr + (NN + 1), col12, invc + NN, aggh, aggl, 0, H0);
    cudaEventRecord(ev[4], 0);
    aggH_kernel<<<AG1, 256>>>(h1h, h1l, rowptr + (NN + 1), col12, invc + NN, aggh, aggl, H0, NN);
    cudaEventRecord(ev[5], 0);
    cudaStreamWaitEvent(s1, ev[4], 0);
    gemm_mma<128, 128, 128, 1><<<GG0, 256, SMC, s1>>>(
        (unsigned short*)aggh, (unsigned short*)aggl, (unsigned short*)h1h, (unsigned short*)h1l,
        B2, bl2, g2, be2, m2, v2, nullptr, h2h, h2l, nullptr, nullptr, nullptr, 0);
    cudaStreamWaitEvent(s1, ev[5], 0);
    gemm_mma<128, 128, 128, 1><<<GG1, 256, SMC, s1>>>(
        (unsigned short*)aggh, (unsigned short*)aggl, (unsigned short*)h1h, (unsigned short*)h1l,
        B2, bl2, g2, be2, m2, v2, nullptr, h2h, h2l, nullptr, nullptr, nullptr, H0);
    cudaEventRecord(ev[6], s1);

    // ===== conv3 =====
    cudaStreamWaitEvent(0, ev[6], 0);
    aggH_kernel<<<AG0, 256>>>(h2h, h2l, rowptr + 2 * (NN + 1), col12 + EE,
                              invc + 2 * NN, aggh, aggl, 0, H0);
    cudaEventRecord(ev[7], 0);
    aggH_kernel<<<AG1, 256>>>(h2h, h2l, rowptr + 2 * (NN + 1), col12 + EE,
                              invc + 2 * NN, aggh, aggl, H0, NN);
    cudaEventRecord(ev[8], 0);
    cudaStreamWaitEvent(s1, ev[7], 0);
    gemm_mma<128, 128, 128, 1><<<GG0, 256, SMC, s1>>>(
        (unsigned short*)aggh, (unsigned short*)aggl, (unsigned short*)h2h, (unsigned short*)h2l,
        B3, bl3, g3, be3, m3, v3, nullptr, h3h, h3l, nullptr, nullptr, nullptr, 0);
    cudaEventRecord(ev[9], s1);
    cudaStreamWaitEvent(s1, ev[8], 0);
    gemm_mma<128, 128, 128, 1><<<GG1, 256, SMC, s1>>>(
        (unsigned short*)aggh, (unsigned short*)aggl, (unsigned short*)h2h, (unsigned short*)h2l,
        B3, bl3, g3, be3, m3, v3, nullptr, h3h, h3l, nullptr, nullptr, nullptr, H0);
    cudaEventRecord(ev[10], s1);

    // ===== readout MLP: h0 on s0 (overlaps gemm3_h1 on s1), h1 on s1 =====
    cudaStreamWaitEvent(0, ev[9], 0);
    gemm_mma<128, 64, 64, 2><<<GG0, 256, SMM>>>(
        (unsigned short*)h3h, (unsigned short*)h3l, (unsigned short*)xh, (unsigned short*)xl,
        B4, b4, nullptr, nullptr, nullptr, nullptr, nullptr,
        nullptr, nullptr, W5, b5, out, 0);
    gemm_mma<128, 64, 64, 2><<<GG1, 256, SMM, s1>>>(
        (unsigned short*)h3h, (unsigned short*)h3l, (unsigned short*)xh, (unsigned short*)xl,
        B4, b4, nullptr, nullptr, nullptr, nullptr, nullptr,
        nullptr, nullptr, W5, b5, out, H0);
    cudaEventRecord(ev[11], s1);
    cudaStreamWaitEvent(0, ev[11], 0);
}

// round 13
// speedup vs baseline: 1.1383x; 1.1383x over previous
#include <cuda_runtime.h>
#include <cuda_bf16.h>

#define NN 50000
#define EE 800000
#define EPSB 1e-5f
#define SCAN_NBLK ((NN + 255) / 256)   // 196

// ==================== device scratch ====================
__device__ __align__(256) unsigned int g_a1h[NN * 64], g_a1l[NN * 64];
__device__ __align__(256) unsigned int g_aggh[NN * 64], g_aggl[NN * 64];
__device__ __align__(256) unsigned int g_h1h[NN * 64], g_h1l[NN * 64];
__device__ __align__(256) unsigned int g_h2h[NN * 64], g_h2l[NN * 64];
__device__ __align__(256) unsigned int g_h3h[NN * 64], g_h3l[NN * 64];
__device__ __align__(256) unsigned int g_xh[NN * 32], g_xl[NN * 32];
__device__ __align__(256) int   g_cnt[3 * NN];
__device__ __align__(256) float g_invc[3 * NN];
__device__ __align__(256) int   g_rowptr[3 * (NN + 1)];
__device__ __align__(256) int   g_cursor[3 * NN];
__device__ __align__(256) int   g_partial[3 * SCAN_NBLK];
__device__ __align__(256) int2  g_col0e[EE];
__device__ __align__(256) int   g_col12[2 * EE];
__device__ __align__(256) unsigned short g_B1[128 * 256];
__device__ __align__(256) unsigned short g_B2[128 * 512];
__device__ __align__(256) unsigned short g_B3[128 * 512];
__device__ __align__(256) unsigned short g_B4[64 * 384];

// ==================== helpers ====================
__device__ __forceinline__ unsigned int smem_u32(const void* p) {
    unsigned int a;
    asm("{ .reg .u64 t; cvta.to.shared.u64 t, %1; cvt.u32.u64 %0, t; }" : "=r"(a) : "l"(p));
    return a;
}
__device__ __forceinline__ void cp_async16(unsigned int saddr, const void* gaddr) {
    asm volatile("cp.async.cg.shared.global [%0], [%1], 16;" :: "r"(saddr), "l"(gaddr));
}
__device__ __forceinline__ void ldsm_x4(unsigned int* r, unsigned int addr) {
    asm volatile("ldmatrix.sync.aligned.m8n8.x4.shared.b16 {%0,%1,%2,%3}, [%4];"
                 : "=r"(r[0]), "=r"(r[1]), "=r"(r[2]), "=r"(r[3]) : "r"(addr));
}
__device__ __forceinline__ void mma16816(float* d, const unsigned int* a,
                                         unsigned int b0, unsigned int b1) {
    asm volatile("mma.sync.aligned.m16n8k16.row.col.f32.bf16.bf16.f32 "
                 "{%0,%1,%2,%3}, {%4,%5,%6,%7}, {%8,%9}, {%0,%1,%2,%3};"
                 : "+f"(d[0]), "+f"(d[1]), "+f"(d[2]), "+f"(d[3])
                 : "r"(a[0]), "r"(a[1]), "r"(a[2]), "r"(a[3]), "r"(b0), "r"(b1));
}
__device__ __forceinline__ unsigned short f2b(float v) {
    return __bfloat16_as_ushort(__float2bfloat16(v));
}
__device__ __forceinline__ float b2f(unsigned short u) {
    return __bfloat162float(__ushort_as_bfloat16(u));
}
__device__ __forceinline__ void split2(float v0, float v1, unsigned int& ph, unsigned int& pl) {
    unsigned short h0 = f2b(v0), h1 = f2b(v1);
    unsigned short l0 = f2b(v0 - b2f(h0)), l1 = f2b(v1 - b2f(h1));
    ph = (unsigned int)h0 | ((unsigned int)h1 << 16);
    pl = (unsigned int)l0 | ((unsigned int)l1 << 16);
}
__device__ __forceinline__ float plo(unsigned int u) { return __uint_as_float(u << 16); }
__device__ __forceinline__ float phi(unsigned int u) { return __uint_as_float(u & 0xFFFF0000u); }

// ==================== prep helpers ====================
__device__ __forceinline__ void prepB_elem(const float* __restrict__ Wa, int Ka,
                                           const float* __restrict__ Wb, int Kb,
                                           int K, unsigned short* __restrict__ img, int idx) {
    int n = idx / K, k = idx - n * K;
    float w = 0.0f;
    if (k < Ka) w = Wa[n * Ka + k];
    else if (Wb != nullptr && (k - Ka) < Kb) w = Wb[n * Kb + (k - Ka)];
    unsigned short hb = f2b(w);
    unsigned short lb = f2b(w - b2f(hb));
    img[(size_t)n * 2 * K + k] = hb;
    img[(size_t)n * 2 * K + K + k] = lb;
}
#define SX (NN * 32)
#define SB1 (128 * 128)
#define SB2 (128 * 256)
#define SB3 (128 * 256)
#define SB4 (64 * 192)

__global__ void count0_prepB1(const int* __restrict__ e0, int* __restrict__ cnt,
                              const float* __restrict__ W1, unsigned short* __restrict__ B1) {
    int idx = blockIdx.x * blockDim.x + threadIdx.x;
    if (idx < EE) { atomicAdd(&cnt[e0[EE + idx]], 1); return; }
    idx -= EE;
    if (idx < SB1) prepB_elem(W1, 96, nullptr, 0, 128, B1, idx);
}
__global__ void count12_prep(const int* __restrict__ e1, const int* __restrict__ e2,
                             int* __restrict__ cnt,
                             const float* __restrict__ x,
                             unsigned int* __restrict__ xh, unsigned int* __restrict__ xl,
                             const float* __restrict__ Wl2, const float* __restrict__ Wr2,
                             const float* __restrict__ Wl3, const float* __restrict__ Wr3,
                             const float* __restrict__ W4,
                             unsigned short* __restrict__ B2, unsigned short* __restrict__ B3,
                             unsigned short* __restrict__ B4) {
    int idx = blockIdx.x * blockDim.x + threadIdx.x;
    if (idx < EE) { atomicAdd(&cnt[NN + e1[EE + idx]], 1); return; }
    if (idx < 2 * EE) { atomicAdd(&cnt[2 * NN + e2[EE + (idx - EE)]], 1); return; }
    idx -= 2 * EE;
    if (idx < SX) {
        int i = idx >> 5, j = idx & 31;
        float2 v = *(const float2*)(x + (size_t)i * 64 + 2 * j);
        unsigned int ph, pl;
        split2(v.x, v.y, ph, pl);
        xh[idx] = ph;
        xl[idx] = pl;
        return;
    }
    idx -= SX;
    if (idx < SB2) { prepB_elem(Wl2, 128, Wr2, 128, 256, B2, idx); return; }
    idx -= SB2;
    if (idx < SB3) { prepB_elem(Wl3, 128, Wr3, 128, 256, B3, idx); return; }
    idx -= SB3;
    if (idx < SB4) { prepB_elem(W4, 192, nullptr, 0, 192, B4, idx); }
}

// ==================== 2-phase parallel scan (scanB folded into scanC) ====================
__global__ void scanA(const int* __restrict__ cnt, int* __restrict__ partial, int Lbase) {
    int L = Lbase + blockIdx.y;
    int i = blockIdx.x * 256 + threadIdx.x;
    int v = (i < NN) ? cnt[L * NN + i] : 0;
#pragma unroll
    for (int o = 16; o; o >>= 1) v += __shfl_down_sync(0xFFFFFFFF, v, o);
    __shared__ int sw[8];
    if ((threadIdx.x & 31) == 0) sw[threadIdx.x >> 5] = v;
    __syncthreads();
    if (threadIdx.x < 8) {
        int s = sw[threadIdx.x];
#pragma unroll
        for (int o = 4; o; o >>= 1) s += __shfl_down_sync(0xFF, s, o);
        if (threadIdx.x == 0) partial[L * SCAN_NBLK + blockIdx.x] = s;
    }
}
// scanC: computes its own base = sum of partials[0..bx) in-block, then per-block
// exclusive scan and emit.
__global__ void scanC(const int* __restrict__ cnt, const int* __restrict__ partial,
                      int* __restrict__ rowptr, int* __restrict__ cursor,
                      float* __restrict__ invc, int Lbase) {
    int L = Lbase + blockIdx.y;
    int t = threadIdx.x;

    // base = sum of partials of preceding blocks
    __shared__ int sbase;
    {
        int pv = (t < blockIdx.x) ? partial[L * SCAN_NBLK + t] : 0;
#pragma unroll
        for (int o = 16; o; o >>= 1) pv += __shfl_down_sync(0xFFFFFFFF, pv, o);
        __shared__ int sw[8];
        if ((t & 31) == 0) sw[t >> 5] = pv;
        __syncthreads();
        if (t < 8) {
            int s = sw[t];
#pragma unroll
            for (int o = 4; o; o >>= 1) s += __shfl_down_sync(0xFF, s, o);
            if (t == 0) sbase = s;
        }
        __syncthreads();
    }

    int i = blockIdx.x * 256 + t;
    int c = (i < NN) ? cnt[L * NN + i] : 0;
    __shared__ int sh[256];
    sh[t] = c;
    __syncthreads();
#pragma unroll
    for (int o = 1; o < 256; o <<= 1) {
        int u = (t >= o) ? sh[t - o] : 0;
        __syncthreads();
        sh[t] += u;
        __syncthreads();
    }
    int ex = sh[t] - c + sbase;
    if (i < NN) {
        rowptr[L * (NN + 1) + i] = ex;
        cursor[L * NN + i] = ex;
        invc[L * NN + i] = (c > 0) ? (1.0f / (float)c) : 0.0f;
    }
    if (i == 0) rowptr[L * (NN + 1) + NN] = EE;
}

// ==================== fill kernels ====================
__global__ void fill0(const int* __restrict__ e0, int* __restrict__ cursor,
                      int2* __restrict__ col0e) {
    int i = blockIdx.x * blockDim.x + threadIdx.x;
    if (i >= EE) return;
    int src = e0[i], dst = e0[EE + i];
    int pos = atomicAdd(&cursor[dst], 1);
    col0e[pos] = make_int2(src, i);
}
__global__ void fill12(const int* __restrict__ e1, const int* __restrict__ e2,
                       int* __restrict__ cursor, int* __restrict__ col12) {
    int i = blockIdx.x * blockDim.x + threadIdx.x;
    if (i < EE) {
        int src = e1[i], dst = e1[EE + i];
        int pos = atomicAdd(&cursor[NN + dst], 1);
        col12[pos] = src;
    } else if (i < 2 * EE) {
        int e = i - EE;
        int src = e2[e], dst = e2[EE + e];
        int pos = atomicAdd(&cursor[2 * NN + dst], 1);
        col12[EE + pos] = src;
    }
}

// ==================== aggregation kernels (round-9 LDG form, 4-edge batched) ====================
__global__ void agg1_kernel(const float* __restrict__ x, const float* __restrict__ ea,
                            const int* __restrict__ rowptr, const int2* __restrict__ ce,
                            const float* __restrict__ invc,
                            unsigned int* __restrict__ ah, unsigned int* __restrict__ al) {
    int warp = (blockIdx.x * blockDim.x + threadIdx.x) >> 5;
    int lane = threadIdx.x & 31;
    if (warp >= NN) return;
    int s = rowptr[warp], e = rowptr[warp + 1];
    const float4* X4 = (const float4*)x;
    const float4* E4 = (const float4*)ea;
    const bool isx = lane < 16;
    const bool act = lane < 24;
    const int li = isx ? lane : (lane - 16);
    const float4* S = isx ? X4 : E4;
    float4 a = make_float4(0.f, 0.f, 0.f, 0.f);
    int p = s;
    for (; p + 4 <= e; p += 4) {
        int2 q0 = ce[p], q1 = ce[p + 1], q2 = ce[p + 2], q3 = ce[p + 3];
        if (act) {
            size_t b0 = isx ? ((size_t)q0.x * 16 + li) : ((size_t)q0.y * 8 + li);
            size_t b1 = isx ? ((size_t)q1.x * 16 + li) : ((size_t)q1.y * 8 + li);
            size_t b2 = isx ? ((size_t)q2.x * 16 + li) : ((size_t)q2.y * 8 + li);
            size_t b3 = isx ? ((size_t)q3.x * 16 + li) : ((size_t)q3.y * 8 + li);
            float4 v0 = S[b0], v1 = S[b1], v2 = S[b2], v3 = S[b3];
            a.x += (v0.x + v1.x) + (v2.x + v3.x);
            a.y += (v0.y + v1.y) + (v2.y + v3.y);
            a.z += (v0.z + v1.z) + (v2.z + v3.z);
            a.w += (v0.w + v1.w) + (v2.w + v3.w);
        }
    }
    for (; p < e; p++) {
        int2 q = ce[p];
        if (act) {
            size_t b = isx ? ((size_t)q.x * 16 + li) : ((size_t)q.y * 8 + li);
            float4 v = S[b];
            a.x += v.x; a.y += v.y; a.z += v.z; a.w += v.w;
        }
    }
    float ic = invc[warp];
    uint2 ph = make_uint2(0, 0), pl = make_uint2(0, 0);
    if (act) {
        split2(a.x * ic, a.y * ic, ph.x, pl.x);
        split2(a.z * ic, a.w * ic, ph.y, pl.y);
    }
    ((uint2*)ah)[(size_t)warp * 32 + lane] = ph;
    ((uint2*)al)[(size_t)warp * 32 + lane] = pl;
}

__global__ void aggH_kernel(const unsigned int* __restrict__ hh, const unsigned int* __restrict__ hl,
                            const int* __restrict__ rowptr, const int* __restrict__ col,
                            const float* __restrict__ invc,
                            unsigned int* __restrict__ oh, unsigned int* __restrict__ ol) {
    int warp = (blockIdx.x * blockDim.x + threadIdx.x) >> 5;
    int lane = threadIdx.x & 31;
    if (warp >= NN) return;
    int s = rowptr[warp], e = rowptr[warp + 1];
    const uint4* S = (lane < 16) ? (const uint4*)hh : (const uint4*)hl;
    const int li = lane & 15;
    float a0 = 0.f, a1 = 0.f, a2 = 0.f, a3 = 0.f;
    float a4 = 0.f, a5 = 0.f, a6 = 0.f, a7 = 0.f;
    int p = s;
    for (; p + 4 <= e; p += 4) {
        int c0 = col[p], c1 = col[p + 1], c2 = col[p + 2], c3 = col[p + 3];
        uint4 v0 = S[(size_t)c0 * 16 + li];
        uint4 v1 = S[(size_t)c1 * 16 + li];
        uint4 v2 = S[(size_t)c2 * 16 + li];
        uint4 v3 = S[(size_t)c3 * 16 + li];
        a0 += (plo(v0.x) + plo(v1.x)) + (plo(v2.x) + plo(v3.x));
        a1 += (phi(v0.x) + phi(v1.x)) + (phi(v2.x) + phi(v3.x));
        a2 += (plo(v0.y) + plo(v1.y)) + (plo(v2.y) + plo(v3.y));
        a3 += (phi(v0.y) + phi(v1.y)) + (phi(v2.y) + phi(v3.y));
        a4 += (plo(v0.z) + plo(v1.z)) + (plo(v2.z) + plo(v3.z));
        a5 += (phi(v0.z) + phi(v1.z)) + (phi(v2.z) + phi(v3.z));
        a6 += (plo(v0.w) + plo(v1.w)) + (plo(v2.w) + plo(v3.w));
        a7 += (phi(v0.w) + phi(v1.w)) + (phi(v2.w) + phi(v3.w));
    }
    for (; p < e; p++) {
        uint4 v = S[(size_t)col[p] * 16 + li];
        a0 += plo(v.x); a1 += phi(v.x);
        a2 += plo(v.y); a3 += phi(v.y);
        a4 += plo(v.z); a5 += phi(v.z);
        a6 += plo(v.w); a7 += phi(v.w);
    }
    a0 += __shfl_down_sync(0xFFFFFFFF, a0, 16);
    a1 += __shfl_down_sync(0xFFFFFFFF, a1, 16);
    a2 += __shfl_down_sync(0xFFFFFFFF, a2, 16);
    a3 += __shfl_down_sync(0xFFFFFFFF, a3, 16);
    a4 += __shfl_down_sync(0xFFFFFFFF, a4, 16);
    a5 += __shfl_down_sync(0xFFFFFFFF, a5, 16);
    a6 += __shfl_down_sync(0xFFFFFFFF, a6, 16);
    a7 += __shfl_down_sync(0xFFFFFFFF, a7, 16);
    if (lane < 16) {
        float ic = invc[warp];
        uint4 ph, pl;
        split2(a0 * ic, a1 * ic, ph.x, pl.x);
        split2(a2 * ic, a3 * ic, ph.y, pl.y);
        split2(a4 * ic, a5 * ic, ph.z, pl.z);
        split2(a6 * ic, a7 * ic, ph.w, pl.w);
        ((uint4*)oh)[(size_t)warp * 16 + lane] = ph;
        ((uint4*)ol)[(size_t)warp * 16 + lane] = pl;
    }
}

// ==================== warp-MMA GEMM (split-bf16 fp32 emulation, 2-phase) ====================
template <int K0, int K1, int NCOL, int MODE>
__global__ __launch_bounds__(256, 2)
void gemm_mma(const unsigned short* __restrict__ A0h, const unsigned short* __restrict__ A0l,
              const unsigned short* __restrict__ A1h, const unsigned short* __restrict__ A1l,
              const unsigned short* __restrict__ Bp,
              const float* __restrict__ bias,
              const float* __restrict__ gamma, const float* __restrict__ beta,
              const float* __restrict__ mean, const float* __restrict__ var,
              const float* __restrict__ invc,
              unsigned int* __restrict__ outHi, unsigned int* __restrict__ outLo,
              const float* __restrict__ W5, const float* __restrict__ b5,
              float* __restrict__ finalOut) {
    constexpr int K = K0 + K1;
    constexpr int P = K / 64;
    constexpr int NCHUNK = 2 * P;
    constexpr int ABYTES = 128 * 128;
    constexpr int BBYTES = NCOL * 128;
    constexpr int STAGE = ABYTES + 2 * BBYTES;
    constexpr int WNC = NCOL / 2;
    constexpr int NI = WNC / 8;

    extern __shared__ char smem[];
    const unsigned int sbase = smem_u32(smem);

    const int tid = threadIdx.x;
    const int lane = tid & 31;
    const int warp = tid >> 5;
    const int wr = warp & 3;
    const int wc = warp >> 2;
    const int brow = blockIdx.x * 128;

    const int lane16 = lane & 15;
    const int lhalf = lane >> 4;
    const int swz = lane16 & 7;

    float acc[2][NI][4];
#pragma unroll
    for (int mi = 0; mi < 2; mi++)
#pragma unroll
        for (int ni = 0; ni < NI; ni++)
#pragma unroll
            for (int q = 0; q < 4; q++) acc[mi][ni][q] = 0.0f;

    for (int cc = 0; cc <= NCHUNK; cc++) {
        if (cc < NCHUNK) {
            const int stage = cc & 1;
            const bool ph1 = cc < P;
            const int kk = (ph1 ? cc : cc - P) * 64;
            const unsigned short* A0 = ph1 ? A0h : A0l;
            const unsigned short* A1 = ph1 ? A1h : A1l;
            const unsigned int sA = sbase + stage * STAGE;
            const unsigned int sB0 = sA + ABYTES;
            const unsigned int sB1 = sB0 + BBYTES;
#pragma unroll
            for (int i = 0; i < 4; i++) {
                int idx = tid + i * 256;
                int r = idx >> 3, c = idx & 7;
                int rg = min(brow + r, NN - 1);
                int ke = kk + c * 8;
                const unsigned short* g =
                    (K1 == 0 || ke < K0) ? (A0 + (size_t)rg * K0 + ke)
                                         : (A1 + (size_t)rg * K1 + (ke - K0));
                cp_async16(sA + r * 128 + ((c ^ (r & 7)) << 4), g);
            }
#pragma unroll
            for (int i = 0; i < (NCOL * 8) / 256; i++) {
                int idx = tid + i * 256;
                int n = idx >> 3, c = idx & 7;
                cp_async16(sB0 + n * 128 + ((c ^ (n & 7)) << 4),
                           Bp + (size_t)n * (2 * K) + kk + c * 8);
            }
            if (ph1) {
#pragma unroll
                for (int i = 0; i < (NCOL * 8) / 256; i++) {
                    int idx = tid + i * 256;
                    int n = idx >> 3, c = idx & 7;
                    cp_async16(sB1 + n * 128 + ((c ^ (n & 7)) << 4),
                               Bp + (size_t)n * (2 * K) + K + kk + c * 8);
                }
            }
            asm volatile("cp.async.commit_group;");
        }
        if (cc == 0) continue;
        if (cc < NCHUNK) asm volatile("cp.async.wait_group 1;");
        else asm volatile("cp.async.wait_group 0;");
        __syncthreads();

        const int stage = (cc - 1) & 1;
        const bool ph = (cc - 1) < P;
        const unsigned int sA = sbase + stage * STAGE;
        const unsigned int sB0 = sA + ABYTES;
#pragma unroll
        for (int ks = 0; ks < 4; ks++) {
            const unsigned int coff = (unsigned int)((((ks << 1) | lhalf) ^ swz) << 4);
            unsigned int a[2][4];
#pragma unroll
            for (int mi = 0; mi < 2; mi++)
                ldsm_x4(a[mi], sA + (wr * 32 + mi * 16 + lane16) * 128 + coff);
#pragma unroll
            for (int h = 0; h < 2; h++) {
                if (h == 1 && !ph) break;
                const unsigned int sB = sB0 + h * BBYTES;
                unsigned int b[NI][2];
#pragma unroll
                for (int nb = 0; nb < NI / 2; nb++) {
                    unsigned int r4[4];
                    ldsm_x4(r4, sB + (wc * WNC + nb * 16 + lane16) * 128 + coff);
                    b[nb * 2][0] = r4[0];
                    b[nb * 2 + 1][0] = r4[1];
                    b[nb * 2][1] = r4[2];
                    b[nb * 2 + 1][1] = r4[3];
                }
#pragma unroll
                for (int mi = 0; mi < 2; mi++)
#pragma unroll
                    for (int ni = 0; ni < NI; ni++)
                        mma16816(acc[mi][ni], a[mi], b[ni][0], b[ni][1]);
            }
        }
        __syncthreads();
    }

    // ---- epilogue ----
    if (MODE == 2) {
        float* part = (float*)smem;
        const int g = lane >> 2, tg = lane & 3;
        float w5b = __ldg(b5);
#pragma unroll
        for (int mi = 0; mi < 2; mi++) {
            float p0 = 0.0f, p1 = 0.0f;
#pragma unroll
            for (int ni = 0; ni < NI; ni++) {
                int cb = wc * WNC + ni * 8 + tg * 2;
                float w0 = __ldg(W5 + cb), w1 = __ldg(W5 + cb + 1);
                float b0 = __ldg(bias + cb), b1 = __ldg(bias + cb + 1);
                p0 += fmaxf(acc[mi][ni][0] + b0, 0.0f) * w0 +
                      fmaxf(acc[mi][ni][1] + b1, 0.0f) * w1;
                p1 += fmaxf(acc[mi][ni][2] + b0, 0.0f) * w0 +
                      fmaxf(acc[mi][ni][3] + b1, 0.0f) * w1;
            }
            p0 += __shfl_xor_sync(0xFFFFFFFF, p0, 1);
            p0 += __shfl_xor_sync(0xFFFFFFFF, p0, 2);
            p1 += __shfl_xor_sync(0xFFFFFFFF, p1, 1);
            p1 += __shfl_xor_sync(0xFFFFFFFF, p1, 2);
            if (tg == 0) {
                part[(wr * 32 + mi * 16 + g) * 2 + wc] = p0;
                part[(wr * 32 + mi * 16 + 8 + g) * 2 + wc] = p1;
            }
        }
        __syncthreads();
        if (tid < 128) {
            int row = brow + tid;
            if (row < NN) finalOut[row] = part[tid * 2] + part[tid * 2 + 1] + w5b;
        }
        return;
    }

    float* sc = (float*)smem;
    float* sf = sc + NCOL;
    float* bi = sf + NCOL;
    if (tid < NCOL) {
        float s = gamma[tid] * rsqrtf(var[tid] + EPSB);
        sc[tid] = s;
        sf[tid] = beta[tid] - mean[tid] * s;
        bi[tid] = bias[tid];
    }
    __syncthreads();

    const int g = lane >> 2, tg = lane & 3;
#pragma unroll
    for (int mi = 0; mi < 2; mi++) {
        int row0 = brow + wr * 32 + mi * 16 + g;
        int row1 = row0 + 8;
        float msk0 = 1.0f, msk1 = 1.0f;
        if (MODE == 0) {
            msk0 = (row0 < NN && invc[row0] > 0.0f) ? 1.0f : 0.0f;
            msk1 = (row1 < NN && invc[row1] > 0.0f) ? 1.0f : 0.0f;
        }
#pragma unroll
        for (int ni = 0; ni < NI; ni++) {
            int cb = wc * WNC + ni * 8 + tg * 2;
            float s0 = sc[cb], s1 = sc[cb + 1];
            float f0 = sf[cb], f1 = sf[cb + 1];
            float b0 = bi[cb], b1 = bi[cb + 1];
            if (row0 < NN) {
                float v0 = acc[mi][ni][0] + b0, v1 = acc[mi][ni][1] + b1;
                if (MODE == 0) { v0 = fmaxf(v0, 0.f) * msk0; v1 = fmaxf(v1, 0.f) * msk0; }
                v0 = fmaxf(s0 * v0 + f0, 0.0f);
                v1 = fmaxf(s1 * v1 + f1, 0.0f);
                unsigned int ph, pl;
                split2(v0, v1, ph, pl);
                outHi[(size_t)row0 * 64 + (cb >> 1)] = ph;
                outLo[(size_t)row0 * 64 + (cb >> 1)] = pl;
            }
            if (row1 < NN) {
                float v0 = acc[mi][ni][2] + b0, v1 = acc[mi][ni][3] + b1;
                if (MODE == 0) { v0 = fmaxf(v0, 0.f) * msk1; v1 = fmaxf(v1, 0.f) * msk1; }
                v0 = fmaxf(s0 * v0 + f0, 0.0f);
                v1 = fmaxf(s1 * v1 + f1, 0.0f);
                unsigned int ph, pl;
                split2(v0, v1, ph, pl);
                outHi[(size_t)row1 * 64 + (cb >> 1)] = ph;
                outLo[(size_t)row1 * 64 + (cb >> 1)] = pl;
            }
        }
    }
}

// ==================== launch (round-11 structure: 2-stream CSR fork) ====================
extern "C" void kernel_launch(void* const* d_in, const int* in_sizes, int n_in,
                              void* d_out, int out_size) {
    const float* x   = (const float*)d_in[0];
    const int*   ei0 = (const int*)d_in[1];
    const int*   ei1 = (const int*)d_in[2];
    const int*   ei2 = (const int*)d_in[3];
    const float* ea  = (const float*)d_in[4];
    const float* W1  = (const float*)d_in[5];
    const float* b1  = (const float*)d_in[6];
    const float* g1  = (const float*)d_in[7];
    const float* be1 = (const float*)d_in[8];
    const float* m1  = (const float*)d_in[9];
    const float* v1  = (const float*)d_in[10];
    const float* Wl2 = (const float*)d_in[11];
    const float* bl2 = (const float*)d_in[12];
    const float* Wr2 = (const float*)d_in[13];
    const float* g2  = (const float*)d_in[14];
    const float* be2 = (const float*)d_in[15];
    const float* m2  = (const float*)d_in[16];
    const float* v2  = (const float*)d_in[17];
    const float* Wl3 = (const float*)d_in[18];
    const float* bl3 = (const float*)d_in[19];
    const float* Wr3 = (const float*)d_in[20];
    const float* g3  = (const float*)d_in[21];
    const float* be3 = (const float*)d_in[22];
    const float* m3  = (const float*)d_in[23];
    const float* v3  = (const float*)d_in[24];
    const float* W4  = (const float*)d_in[25];
    const float* b4  = (const float*)d_in[26];
    const float* W5  = (const float*)d_in[27];
    const float* b5  = (const float*)d_in[28];
    float* out = (float*)d_out;

    unsigned int *a1h, *a1l, *aggh, *aggl, *h1h, *h1l, *h2h, *h2l, *h3h, *h3l, *xh, *xl;
    float *invc;
    int *cnt, *rowptr, *cursor, *col12, *partial;
    int2* col0e;
    unsigned short *B1, *B2, *B3, *B4;
    cudaGetSymbolAddress((void**)&a1h, g_a1h);   cudaGetSymbolAddress((void**)&a1l, g_a1l);
    cudaGetSymbolAddress((void**)&aggh, g_aggh); cudaGetSymbolAddress((void**)&aggl, g_aggl);
    cudaGetSymbolAddress((void**)&h1h, g_h1h);   cudaGetSymbolAddress((void**)&h1l, g_h1l);
    cudaGetSymbolAddress((void**)&h2h, g_h2h);   cudaGetSymbolAddress((void**)&h2l, g_h2l);
    cudaGetSymbolAddress((void**)&h3h, g_h3h);   cudaGetSymbolAddress((void**)&h3l, g_h3l);
    cudaGetSymbolAddress((void**)&xh, g_xh);     cudaGetSymbolAddress((void**)&xl, g_xl);
    cudaGetSymbolAddress((void**)&cnt, g_cnt);
    cudaGetSymbolAddress((void**)&invc, g_invc);
    cudaGetSymbolAddress((void**)&rowptr, g_rowptr);
    cudaGetSymbolAddress((void**)&cursor, g_cursor);
    cudaGetSymbolAddress((void**)&partial, g_partial);
    cudaGetSymbolAddress((void**)&col0e, g_col0e);
    cudaGetSymbolAddress((void**)&col12, g_col12);
    cudaGetSymbolAddress((void**)&B1, g_B1);
    cudaGetSymbolAddress((void**)&B2, g_B2);
    cudaGetSymbolAddress((void**)&B3, g_B3);
    cudaGetSymbolAddress((void**)&B4, g_B4);

    const int SMC = 2 * (128 * 128 + 2 * 128 * 128);  // 98304
    const int SMM = 2 * (128 * 128 + 2 * 64 * 128);   // 65536
    cudaFuncSetAttribute(gemm_mma<128, 0, 128, 0>,
                         cudaFuncAttributeMaxDynamicSharedMemorySize, SMC);
    cudaFuncSetAttribute(gemm_mma<128, 128, 128, 1>,
                         cudaFuncAttributeMaxDynamicSharedMemorySize, SMC);
    cudaFuncSetAttribute(gemm_mma<128, 64, 64, 2>,
                         cudaFuncAttributeMaxDynamicSharedMemorySize, SMM);

    // one-time stream/event setup (resources only; identical work every call)
    static cudaStream_t s1 = nullptr;
    static cudaEvent_t evRoot = nullptr, evB = nullptr;
    if (s1 == nullptr) {
        cudaStreamCreateWithFlags(&s1, cudaStreamNonBlocking);
        cudaEventCreateWithFlags(&evRoot, cudaEventDisableTiming);
        cudaEventCreateWithFlags(&evB, cudaEventDisableTiming);
    }

    const int agg_grid = (NN + 7) / 8;
    const int G = (NN + 127) / 128;  // 391
    dim3 scan0_grid(SCAN_NBLK, 1);
    dim3 scan12_grid(SCAN_NBLK, 2);

    // ---- root: zero counts, then fork ----
    cudaMemsetAsync(cnt, 0, 3 * NN * sizeof(int), 0);
    cudaEventRecord(evRoot, 0);
    cudaStreamWaitEvent(s1, evRoot, 0);

    // ---- side stream s1: lists 1,2 CSR + heavy prep ----
    count12_prep<<<(2 * EE + SX + SB2 + SB3 + SB4 + 255) / 256, 256, 0, s1>>>(
        ei1, ei2, cnt, x, xh, xl, Wl2, Wr2, Wl3, Wr3, W4, B2, B3, B4);
    scanA<<<scan12_grid, 256, 0, s1>>>(cnt, partial, 1);
    scanC<<<scan12_grid, 256, 0, s1>>>(cnt, partial, rowptr, cursor, invc, 1);
    fill12<<<(2 * EE + 255) / 256, 256, 0, s1>>>(ei1, ei2, cursor, col12);
    cudaEventRecord(evB, s1);

    // ---- critical stream 0: list0 CSR -> conv1 ----
    count0_prepB1<<<(EE + SB1 + 255) / 256, 256>>>(ei0, cnt, W1, B1);
    scanA<<<scan0_grid, 256>>>(cnt, partial, 0);
    scanC<<<scan0_grid, 256>>>(cnt, partial, rowptr, cursor, invc, 0);
    fill0<<<(EE + 255) / 256, 256>>>(ei0, cursor, col0e);
    agg1_kernel<<<agg_grid, 256>>>(x, ea, rowptr, col0e, invc, a1h, a1l);
    gemm_mma<128, 0, 128, 0><<<G, 256, SMC>>>(
        (unsigned short*)a1h, (unsigned short*)a1l,
        (unsigned short*)a1h, (unsigned short*)a1l,
        B1, b1, g1, be1, m1, v1, invc, h1h, h1l, nullptr, nullptr, nullptr);

    // ---- join ----
    cudaStreamWaitEvent(0, evB, 0);

    // conv2
    aggH_kernel<<<agg_grid, 256>>>(h1h, h1l, rowptr + (NN + 1), col12, invc + NN, aggh, aggl);
    gemm_mma<128, 128, 128, 1><<<G, 256, SMC>>>(
        (unsigned short*)aggh, (unsigned short*)aggl,
        (unsigned short*)h1h, (unsigned short*)h1l,
        B2, bl2, g2, be2, m2, v2, nullptr, h2h, h2l, nullptr, nullptr, nullptr);
    // conv3
    aggH_kernel<<<agg_grid, 256>>>(h2h, h2l, rowptr + 2 * (NN + 1), col12 + EE,
                                   invc + 2 * NN, aggh, aggl);
    gemm_mma<128, 128, 128, 1><<<G, 256, SMC>>>(
        (unsigned short*)aggh, (unsigned short*)aggl,
        (unsigned short*)h2h, (unsigned short*)h2l,
        B3, bl3, g3, be3, m3, v3, nullptr, h3h, h3l, nullptr, nullptr, nullptr);
    // readout MLP + fused W5 dot
    gemm_mma<128, 64, 64, 2><<<G, 256, SMM>>>(
        (unsigned short*)h3h, (unsigned short*)h3l,
        (unsigned short*)xh, (unsigned short*)xl,
        B4, b4, nullptr, nullptr, nullptr, nullptr, nullptr,
        nullptr, nullptr, W5, b5, out);
}

// round 14
// speedup vs baseline: 1.1452x; 1.0060x over previous
#include <cuda_runtime.h>
#include <cuda_bf16.h>
#include <cuda_fp16.h>

#define NN 50000
#define EE 800000
#define EPSB 1e-5f
#define SCAN_NBLK ((NN + 255) / 256)   // 196

// ==================== device scratch ====================
__device__ __align__(256) unsigned int g_a1h[NN * 64], g_a1l[NN * 64];
__device__ __align__(256) unsigned int g_aggh[NN * 64], g_aggl[NN * 64];
__device__ __align__(256) unsigned int g_h1h[NN * 64], g_h1l[NN * 64];
__device__ __align__(256) unsigned int g_h2h[NN * 64], g_h2l[NN * 64];
__device__ __align__(256) unsigned int g_h3h[NN * 64], g_h3l[NN * 64];
__device__ __align__(256) unsigned int g_h1f[NN * 64], g_h2f[NN * 64];  // fp16 mirrors
__device__ __align__(256) unsigned int g_xf[NN * 32];                    // x fp16 mirror
__device__ __align__(256) unsigned int g_xh[NN * 32], g_xl[NN * 32];
__device__ __align__(256) int   g_cnt[3 * NN];
__device__ __align__(256) float g_invc[3 * NN];
__device__ __align__(256) int   g_rowptr[3 * (NN + 1)];
__device__ __align__(256) int   g_cursor[3 * NN];
__device__ __align__(256) int   g_partial[3 * SCAN_NBLK];
__device__ __align__(256) int2  g_col0e[EE];
__device__ __align__(256) int   g_col12[2 * EE];
__device__ __align__(256) unsigned short g_B1[128 * 256];
__device__ __align__(256) unsigned short g_B2[128 * 512];
__device__ __align__(256) unsigned short g_B3[128 * 512];
__device__ __align__(256) unsigned short g_B4[64 * 384];

// ==================== helpers ====================
__device__ __forceinline__ unsigned int smem_u32(const void* p) {
    unsigned int a;
    asm("{ .reg .u64 t; cvta.to.shared.u64 t, %1; cvt.u32.u64 %0, t; }" : "=r"(a) : "l"(p));
    return a;
}
__device__ __forceinline__ void cp_async16(unsigned int saddr, const void* gaddr) {
    asm volatile("cp.async.cg.shared.global [%0], [%1], 16;" :: "r"(saddr), "l"(gaddr));
}
__device__ __forceinline__ void ldsm_x4(unsigned int* r, unsigned int addr) {
    asm volatile("ldmatrix.sync.aligned.m8n8.x4.shared.b16 {%0,%1,%2,%3}, [%4];"
                 : "=r"(r[0]), "=r"(r[1]), "=r"(r[2]), "=r"(r[3]) : "r"(addr));
}
__device__ __forceinline__ void mma16816(float* d, const unsigned int* a,
                                         unsigned int b0, unsigned int b1) {
    asm volatile("mma.sync.aligned.m16n8k16.row.col.f32.bf16.bf16.f32 "
                 "{%0,%1,%2,%3}, {%4,%5,%6,%7}, {%8,%9}, {%0,%1,%2,%3};"
                 : "+f"(d[0]), "+f"(d[1]), "+f"(d[2]), "+f"(d[3])
                 : "r"(a[0]), "r"(a[1]), "r"(a[2]), "r"(a[3]), "r"(b0), "r"(b1));
}
__device__ __forceinline__ unsigned short f2b(float v) {
    return __bfloat16_as_ushort(__float2bfloat16(v));
}
__device__ __forceinline__ float b2f(unsigned short u) {
    return __bfloat162float(__ushort_as_bfloat16(u));
}
__device__ __forceinline__ void split2(float v0, float v1, unsigned int& ph, unsigned int& pl) {
    unsigned short h0 = f2b(v0), h1 = f2b(v1);
    unsigned short l0 = f2b(v0 - b2f(h0)), l1 = f2b(v1 - b2f(h1));
    ph = (unsigned int)h0 | ((unsigned int)h1 << 16);
    pl = (unsigned int)l0 | ((unsigned int)l1 << 16);
}
__device__ __forceinline__ float plo(unsigned int u) { return __uint_as_float(u << 16); }
__device__ __forceinline__ float phi(unsigned int u) { return __uint_as_float(u & 0xFFFF0000u); }
__device__ __forceinline__ unsigned int pack_h2(float v0, float v1) {
    __half2 h = __floats2half2_rn(v0, v1);
    return *(unsigned int*)&h;
}
__device__ __forceinline__ float2 h2f2(unsigned int u) {
    return __half22float2(*(__half2*)&u);
}
// accumulate 8 fp16 values from a uint4 into a[0..7]
__device__ __forceinline__ void acc8(float* a, uint4 v) {
    float2 f;
    f = h2f2(v.x); a[0] += f.x; a[1] += f.y;
    f = h2f2(v.y); a[2] += f.x; a[3] += f.y;
    f = h2f2(v.z); a[4] += f.x; a[5] += f.y;
    f = h2f2(v.w); a[6] += f.x; a[7] += f.y;
}

// ==================== prep helpers ====================
__device__ __forceinline__ void prepB_elem(const float* __restrict__ Wa, int Ka,
                                           const float* __restrict__ Wb, int Kb,
                                           int K, unsigned short* __restrict__ img, int idx) {
    int n = idx / K, k = idx - n * K;
    float w = 0.0f;
    if (k < Ka) w = Wa[n * Ka + k];
    else if (Wb != nullptr && (k - Ka) < Kb) w = Wb[n * Kb + (k - Ka)];
    unsigned short hb = f2b(w);
    unsigned short lb = f2b(w - b2f(hb));
    img[(size_t)n * 2 * K + k] = hb;
    img[(size_t)n * 2 * K + K + k] = lb;
}
#define SX (NN * 32)
#define SXF (NN * 16)
#define SB1 (128 * 128)
#define SB2 (128 * 256)
#define SB3 (128 * 256)
#define SB4 (64 * 192)

// critical-path: count list0 + prep B1 + x fp16 mirror (needed by agg1)
__global__ void count0_prepB1(const int* __restrict__ e0, int* __restrict__ cnt,
                              const float* __restrict__ W1, unsigned short* __restrict__ B1,
                              const float* __restrict__ x, unsigned int* __restrict__ xf) {
    int idx = blockIdx.x * blockDim.x + threadIdx.x;
    if (idx < EE) { atomicAdd(&cnt[e0[EE + idx]], 1); return; }
    idx -= EE;
    if (idx < SB1) { prepB_elem(W1, 96, nullptr, 0, 128, B1, idx); return; }
    idx -= SB1;
    if (idx < SXF) {
        float4 v = ((const float4*)x)[idx];
        ((uint2*)xf)[idx] = make_uint2(pack_h2(v.x, v.y), pack_h2(v.z, v.w));
    }
}
__global__ void count12_prep(const int* __restrict__ e1, const int* __restrict__ e2,
                             int* __restrict__ cnt,
                             const float* __restrict__ x,
                             unsigned int* __restrict__ xh, unsigned int* __restrict__ xl,
                             const float* __restrict__ Wl2, const float* __restrict__ Wr2,
                             const float* __restrict__ Wl3, const float* __restrict__ Wr3,
                             const float* __restrict__ W4,
                             unsigned short* __restrict__ B2, unsigned short* __restrict__ B3,
                             unsigned short* __restrict__ B4) {
    int idx = blockIdx.x * blockDim.x + threadIdx.x;
    if (idx < EE) { atomicAdd(&cnt[NN + e1[EE + idx]], 1); return; }
    if (idx < 2 * EE) { atomicAdd(&cnt[2 * NN + e2[EE + (idx - EE)]], 1); return; }
    idx -= 2 * EE;
    if (idx < SX) {
        int i = idx >> 5, j = idx & 31;
        float2 v = *(const float2*)(x + (size_t)i * 64 + 2 * j);
        unsigned int ph, pl;
        split2(v.x, v.y, ph, pl);
        xh[idx] = ph;
        xl[idx] = pl;
        return;
    }
    idx -= SX;
    if (idx < SB2) { prepB_elem(Wl2, 128, Wr2, 128, 256, B2, idx); return; }
    idx -= SB2;
    if (idx < SB3) { prepB_elem(Wl3, 128, Wr3, 128, 256, B3, idx); return; }
    idx -= SB3;
    if (idx < SB4) { prepB_elem(W4, 192, nullptr, 0, 192, B4, idx); }
}

// ==================== 2-phase parallel scan ====================
__global__ void scanA(const int* __restrict__ cnt, int* __restrict__ partial, int Lbase) {
    int L = Lbase + blockIdx.y;
    int i = blockIdx.x * 256 + threadIdx.x;
    int v = (i < NN) ? cnt[L * NN + i] : 0;
#pragma unroll
    for (int o = 16; o; o >>= 1) v += __shfl_down_sync(0xFFFFFFFF, v, o);
    __shared__ int sw[8];
    if ((threadIdx.x & 31) == 0) sw[threadIdx.x >> 5] = v;
    __syncthreads();
    if (threadIdx.x < 8) {
        int s = sw[threadIdx.x];
#pragma unroll
        for (int o = 4; o; o >>= 1) s += __shfl_down_sync(0xFF, s, o);
        if (threadIdx.x == 0) partial[L * SCAN_NBLK + blockIdx.x] = s;
    }
}
__global__ void scanC(const int* __restrict__ cnt, const int* __restrict__ partial,
                      int* __restrict__ rowptr, int* __restrict__ cursor,
                      float* __restrict__ invc, int Lbase) {
    int L = Lbase + blockIdx.y;
    int t = threadIdx.x;
    __shared__ int sbase;
    {
        int pv = (t < blockIdx.x) ? partial[L * SCAN_NBLK + t] : 0;
#pragma unroll
        for (int o = 16; o; o >>= 1) pv += __shfl_down_sync(0xFFFFFFFF, pv, o);
        __shared__ int sw[8];
        if ((t & 31) == 0) sw[t >> 5] = pv;
        __syncthreads();
        if (t < 8) {
            int s = sw[t];
#pragma unroll
            for (int o = 4; o; o >>= 1) s += __shfl_down_sync(0xFF, s, o);
            if (t == 0) sbase = s;
        }
        __syncthreads();
    }
    int i = blockIdx.x * 256 + t;
    int c = (i < NN) ? cnt[L * NN + i] : 0;
    __shared__ int sh[256];
    sh[t] = c;
    __syncthreads();
#pragma unroll
    for (int o = 1; o < 256; o <<= 1) {
        int u = (t >= o) ? sh[t - o] : 0;
        __syncthreads();
        sh[t] += u;
        __syncthreads();
    }
    int ex = sh[t] - c + sbase;
    if (i < NN) {
        rowptr[L * (NN + 1) + i] = ex;
        cursor[L * NN + i] = ex;
        invc[L * NN + i] = (c > 0) ? (1.0f / (float)c) : 0.0f;
    }
    if (i == 0) rowptr[L * (NN + 1) + NN] = EE;
}

// ==================== fill kernels ====================
__global__ void fill0(const int* __restrict__ e0, int* __restrict__ cursor,
                      int2* __restrict__ col0e) {
    int i = blockIdx.x * blockDim.x + threadIdx.x;
    if (i >= EE) return;
    int src = e0[i], dst = e0[EE + i];
    int pos = atomicAdd(&cursor[dst], 1);
    col0e[pos] = make_int2(src, i);
}
__global__ void fill12(const int* __restrict__ e1, const int* __restrict__ e2,
                       int* __restrict__ cursor, int* __restrict__ col12) {
    int i = blockIdx.x * blockDim.x + threadIdx.x;
    if (i < EE) {
        int src = e1[i], dst = e1[EE + i];
        int pos = atomicAdd(&cursor[NN + dst], 1);
        col12[pos] = src;
    } else if (i < 2 * EE) {
        int e = i - EE;
        int src = e2[e], dst = e2[EE + e];
        int pos = atomicAdd(&cursor[2 * NN + dst], 1);
        col12[EE + pos] = src;
    }
}

// ==================== aggregation kernels (fp16 gathers) ====================
// conv1: lanes 0-15 gather xf (uint2, fp16), lanes 16-23 gather ea (float4), 24-31 pad.
__global__ void agg1_kernel(const unsigned int* __restrict__ xf, const float* __restrict__ ea,
                            const int* __restrict__ rowptr, const int2* __restrict__ ce,
                            const float* __restrict__ invc,
                            unsigned int* __restrict__ ah, unsigned int* __restrict__ al) {
    int warp = (blockIdx.x * blockDim.x + threadIdx.x) >> 5;
    int lane = threadIdx.x & 31;
    if (warp >= NN) return;
    int s = rowptr[warp], e = rowptr[warp + 1];
    const uint2* X2 = (const uint2*)xf;     // 16 uint2 per row
    const float4* E4 = (const float4*)ea;
    const bool isx = lane < 16;
    const bool act = lane < 24;
    const int li = isx ? lane : (lane - 16);
    float a0 = 0.f, a1 = 0.f, a2 = 0.f, a3 = 0.f;
    int p = s;
    for (; p + 4 <= e; p += 4) {
        int2 q0 = ce[p], q1 = ce[p + 1], q2 = ce[p + 2], q3 = ce[p + 3];
        if (isx) {
            uint2 u0 = X2[(size_t)q0.x * 16 + li];
            uint2 u1 = X2[(size_t)q1.x * 16 + li];
            uint2 u2 = X2[(size_t)q2.x * 16 + li];
            uint2 u3 = X2[(size_t)q3.x * 16 + li];
            float2 f;
            f = h2f2(u0.x); a0 += f.x; a1 += f.y;
            f = h2f2(u0.y); a2 += f.x; a3 += f.y;
            f = h2f2(u1.x); a0 += f.x; a1 += f.y;
            f = h2f2(u1.y); a2 += f.x; a3 += f.y;
            f = h2f2(u2.x); a0 += f.x; a1 += f.y;
            f = h2f2(u2.y); a2 += f.x; a3 += f.y;
            f = h2f2(u3.x); a0 += f.x; a1 += f.y;
            f = h2f2(u3.y); a2 += f.x; a3 += f.y;
        } else if (act) {
            float4 v0 = E4[(size_t)q0.y * 8 + li];
            float4 v1 = E4[(size_t)q1.y * 8 + li];
            float4 v2 = E4[(size_t)q2.y * 8 + li];
            float4 v3 = E4[(size_t)q3.y * 8 + li];
            a0 += (v0.x + v1.x) + (v2.x + v3.x);
            a1 += (v0.y + v1.y) + (v2.y + v3.y);
            a2 += (v0.z + v1.z) + (v2.z + v3.z);
            a3 += (v0.w + v1.w) + (v2.w + v3.w);
        }
    }
    for (; p < e; p++) {
        int2 q = ce[p];
        if (isx) {
            uint2 u = X2[(size_t)q.x * 16 + li];
            float2 f;
            f = h2f2(u.x); a0 += f.x; a1 += f.y;
            f = h2f2(u.y); a2 += f.x; a3 += f.y;
        } else if (act) {
            float4 v = E4[(size_t)q.y * 8 + li];
            a0 += v.x; a1 += v.y; a2 += v.z; a3 += v.w;
        }
    }
    float ic = invc[warp];
    uint2 ph = make_uint2(0, 0), pl = make_uint2(0, 0);
    if (act) {
        split2(a0 * ic, a1 * ic, ph.x, pl.x);
        split2(a2 * ic, a3 * ic, ph.y, pl.y);
    }
    ((uint2*)ah)[(size_t)warp * 32 + lane] = ph;
    ((uint2*)al)[(size_t)warp * 32 + lane] = pl;
}

// SAGE mean over fp16 rows: 2 edges per warp iteration (lanes 0-15 even edges,
// lanes 16-31 odd edges), 8 edges per batch; shfl-combine at the end.
__global__ void aggH_kernel(const unsigned int* __restrict__ hf,
                            const int* __restrict__ rowptr, const int* __restrict__ col,
                            const float* __restrict__ invc,
                            unsigned int* __restrict__ oh, unsigned int* __restrict__ ol) {
    int warp = (blockIdx.x * blockDim.x + threadIdx.x) >> 5;
    int lane = threadIdx.x & 31;
    if (warp >= NN) return;
    int s = rowptr[warp], e = rowptr[warp + 1];
    const uint4* H = (const uint4*)hf;   // 16 uint4 per row (128 fp16)
    const int li = lane & 15;
    const int half = lane >> 4;
    float a[8];
#pragma unroll
    for (int q = 0; q < 8; q++) a[q] = 0.0f;
    int p = s;
    for (; p + 8 <= e; p += 8) {
        int c0 = col[p + half];
        int c1 = col[p + 2 + half];
        int c2 = col[p + 4 + half];
        int c3 = col[p + 6 + half];
        uint4 v0 = H[(size_t)c0 * 16 + li];
        uint4 v1 = H[(size_t)c1 * 16 + li];
        uint4 v2 = H[(size_t)c2 * 16 + li];
        uint4 v3 = H[(size_t)c3 * 16 + li];
        acc8(a, v0); acc8(a, v1); acc8(a, v2); acc8(a, v3);
    }
    for (; p < e; p++) {
        if (lane < 16) {
            uint4 v = H[(size_t)col[p] * 16 + li];
            acc8(a, v);
        }
    }
#pragma unroll
    for (int q = 0; q < 8; q++) a[q] += __shfl_down_sync(0xFFFFFFFF, a[q], 16);
    if (lane < 16) {
        float ic = invc[warp];
        uint4 ph, pl;
        split2(a[0] * ic, a[1] * ic, ph.x, pl.x);
        split2(a[2] * ic, a[3] * ic, ph.y, pl.y);
        split2(a[4] * ic, a[5] * ic, ph.z, pl.z);
        split2(a[6] * ic, a[7] * ic, ph.w, pl.w);
        ((uint4*)oh)[(size_t)warp * 16 + lane] = ph;
        ((uint4*)ol)[(size_t)warp * 16 + lane] = pl;
    }
}

// ==================== warp-MMA GEMM (split-bf16 fp32 emulation, 2-phase) ====================
template <int K0, int K1, int NCOL, int MODE>
__global__ __launch_bounds__(256, 2)
void gemm_mma(const unsigned short* __restrict__ A0h, const unsigned short* __restrict__ A0l,
              const unsigned short* __restrict__ A1h, const unsigned short* __restrict__ A1l,
              const unsigned short* __restrict__ Bp,
              const float* __restrict__ bias,
              const float* __restrict__ gamma, const float* __restrict__ beta,
              const float* __restrict__ mean, const float* __restrict__ var,
              const float* __restrict__ invc,
              unsigned int* __restrict__ outHi, unsigned int* __restrict__ outLo,
              unsigned int* __restrict__ outF16,
              const float* __restrict__ W5, const float* __restrict__ b5,
              float* __restrict__ finalOut) {
    constexpr int K = K0 + K1;
    constexpr int P = K / 64;
    constexpr int NCHUNK = 2 * P;
    constexpr int ABYTES = 128 * 128;
    constexpr int BBYTES = NCOL * 128;
    constexpr int STAGE = ABYTES + 2 * BBYTES;
    constexpr int WNC = NCOL / 2;
    constexpr int NI = WNC / 8;

    extern __shared__ char smem[];
    const unsigned int sbase = smem_u32(smem);

    const int tid = threadIdx.x;
    const int lane = tid & 31;
    const int warp = tid >> 5;
    const int wr = warp & 3;
    const int wc = warp >> 2;
    const int brow = blockIdx.x * 128;

    const int lane16 = lane & 15;
    const int lhalf = lane >> 4;
    const int swz = lane16 & 7;

    float acc[2][NI][4];
#pragma unroll
    for (int mi = 0; mi < 2; mi++)
#pragma unroll
        for (int ni = 0; ni < NI; ni++)
#pragma unroll
            for (int q = 0; q < 4; q++) acc[mi][ni][q] = 0.0f;

    for (int cc = 0; cc <= NCHUNK; cc++) {
        if (cc < NCHUNK) {
            const int stage = cc & 1;
            const bool ph1 = cc < P;
            const int kk = (ph1 ? cc : cc - P) * 64;
            const unsigned short* A0 = ph1 ? A0h : A0l;
            const unsigned short* A1 = ph1 ? A1h : A1l;
            const unsigned int sA = sbase + stage * STAGE;
            const unsigned int sB0 = sA + ABYTES;
            const unsigned int sB1 = sB0 + BBYTES;
#pragma unroll
            for (int i = 0; i < 4; i++) {
                int idx = tid + i * 256;
                int r = idx >> 3, c = idx & 7;
                int rg = min(brow + r, NN - 1);
                int ke = kk + c * 8;
                const unsigned short* g =
                    (K1 == 0 || ke < K0) ? (A0 + (size_t)rg * K0 + ke)
                                         : (A1 + (size_t)rg * K1 + (ke - K0));
                cp_async16(sA + r * 128 + ((c ^ (r & 7)) << 4), g);
            }
#pragma unroll
            for (int i = 0; i < (NCOL * 8) / 256; i++) {
                int idx = tid + i * 256;
                int n = idx >> 3, c = idx & 7;
                cp_async16(sB0 + n * 128 + ((c ^ (n & 7)) << 4),
                           Bp + (size_t)n * (2 * K) + kk + c * 8);
            }
            if (ph1) {
#pragma unroll
                for (int i = 0; i < (NCOL * 8) / 256; i++) {
                    int idx = tid + i * 256;
                    int n = idx >> 3, c = idx & 7;
                    cp_async16(sB1 + n * 128 + ((c ^ (n & 7)) << 4),
                               Bp + (size_t)n * (2 * K) + K + kk + c * 8);
                }
            }
            asm volatile("cp.async.commit_group;");
        }
        if (cc == 0) continue;
        if (cc < NCHUNK) asm volatile("cp.async.wait_group 1;");
        else asm volatile("cp.async.wait_group 0;");
        __syncthreads();

        const int stage = (cc - 1) & 1;
        const bool ph = (cc - 1) < P;
        const unsigned int sA = sbase + stage * STAGE;
        const unsigned int sB0 = sA + ABYTES;
#pragma unroll
        for (int ks = 0; ks < 4; ks++) {
            const unsigned int coff = (unsigned int)((((ks << 1) | lhalf) ^ swz) << 4);
            unsigned int a[2][4];
#pragma unroll
            for (int mi = 0; mi < 2; mi++)
                ldsm_x4(a[mi], sA + (wr * 32 + mi * 16 + lane16) * 128 + coff);
#pragma unroll
            for (int h = 0; h < 2; h++) {
                if (h == 1 && !ph) break;
                const unsigned int sB = sB0 + h * BBYTES;
                unsigned int b[NI][2];
#pragma unroll
                for (int nb = 0; nb < NI / 2; nb++) {
                    unsigned int r4[4];
                    ldsm_x4(r4, sB + (wc * WNC + nb * 16 + lane16) * 128 + coff);
                    b[nb * 2][0] = r4[0];
                    b[nb * 2 + 1][0] = r4[1];
                    b[nb * 2][1] = r4[2];
                    b[nb * 2 + 1][1] = r4[3];
                }
#pragma unroll
                for (int mi = 0; mi < 2; mi++)
#pragma unroll
                    for (int ni = 0; ni < NI; ni++)
                        mma16816(acc[mi][ni], a[mi], b[ni][0], b[ni][1]);
            }
        }
        __syncthreads();
    }

    // ---- epilogue ----
    if (MODE == 2) {
        float* part = (float*)smem;
        const int g = lane >> 2, tg = lane & 3;
        float w5b = __ldg(b5);
#pragma unroll
        for (int mi = 0; mi < 2; mi++) {
            float p0 = 0.0f, p1 = 0.0f;
#pragma unroll
            for (int ni = 0; ni < NI; ni++) {
                int cb = wc * WNC + ni * 8 + tg * 2;
                float w0 = __ldg(W5 + cb), w1 = __ldg(W5 + cb + 1);
                float b0 = __ldg(bias + cb), b1 = __ldg(bias + cb + 1);
                p0 += fmaxf(acc[mi][ni][0] + b0, 0.0f) * w0 +
                      fmaxf(acc[mi][ni][1] + b1, 0.0f) * w1;
                p1 += fmaxf(acc[mi][ni][2] + b0, 0.0f) * w0 +
                      fmaxf(acc[mi][ni][3] + b1, 0.0f) * w1;
            }
            p0 += __shfl_xor_sync(0xFFFFFFFF, p0, 1);
            p0 += __shfl_xor_sync(0xFFFFFFFF, p0, 2);
            p1 += __shfl_xor_sync(0xFFFFFFFF, p1, 1);
            p1 += __shfl_xor_sync(0xFFFFFFFF, p1, 2);
            if (tg == 0) {
                part[(wr * 32 + mi * 16 + g) * 2 + wc] = p0;
                part[(wr * 32 + mi * 16 + 8 + g) * 2 + wc] = p1;
            }
        }
        __syncthreads();
        if (tid < 128) {
            int row = brow + tid;
            if (row < NN) finalOut[row] = part[tid * 2] + part[tid * 2 + 1] + w5b;
        }
        return;
    }

    float* sc = (float*)smem;
    float* sf = sc + NCOL;
    float* bi = sf + NCOL;
    if (tid < NCOL) {
        float s = gamma[tid] * rsqrtf(var[tid] + EPSB);
        sc[tid] = s;
        sf[tid] = beta[tid] - mean[tid] * s;
        bi[tid] = bias[tid];
    }
    __syncthreads();

    const int g = lane >> 2, tg = lane & 3;
#pragma unroll
    for (int mi = 0; mi < 2; mi++) {
        int row0 = brow + wr * 32 + mi * 16 + g;
        int row1 = row0 + 8;
        float msk0 = 1.0f, msk1 = 1.0f;
        if (MODE == 0) {
            msk0 = (row0 < NN && invc[row0] > 0.0f) ? 1.0f : 0.0f;
            msk1 = (row1 < NN && invc[row1] > 0.0f) ? 1.0f : 0.0f;
        }
#pragma unroll
        for (int ni = 0; ni < NI; ni++) {
            int cb = wc * WNC + ni * 8 + tg * 2;
            float s0 = sc[cb], s1 = sc[cb + 1];
            float f0 = sf[cb], f1 = sf[cb + 1];
            float b0 = bi[cb], b1 = bi[cb + 1];
            if (row0 < NN) {
                float v0 = acc[mi][ni][0] + b0, v1 = acc[mi][ni][1] + b1;
                if (MODE == 0) { v0 = fmaxf(v0, 0.f) * msk0; v1 = fmaxf(v1, 0.f) * msk0; }
                v0 = fmaxf(s0 * v0 + f0, 0.0f);
                v1 = fmaxf(s1 * v1 + f1, 0.0f);
                unsigned int ph, pl;
                split2(v0, v1, ph, pl);
                outHi[(size_t)row0 * 64 + (cb >> 1)] = ph;
                outLo[(size_t)row0 * 64 + (cb >> 1)] = pl;
                if (outF16) outF16[(size_t)row0 * 64 + (cb >> 1)] = pack_h2(v0, v1);
            }
            if (row1 < NN) {
                float v0 = acc[mi][ni][2] + b0, v1 = acc[mi][ni][3] + b1;
                if (MODE == 0) { v0 = fmaxf(v0, 0.f) * msk1; v1 = fmaxf(v1, 0.f) * msk1; }
                v0 = fmaxf(s0 * v0 + f0, 0.0f);
                v1 = fmaxf(s1 * v1 + f1, 0.0f);
                unsigned int ph, pl;
                split2(v0, v1, ph, pl);
                outHi[(size_t)row1 * 64 + (cb >> 1)] = ph;
                outLo[(size_t)row1 * 64 + (cb >> 1)] = pl;
                if (outF16) outF16[(size_t)row1 * 64 + (cb >> 1)] = pack_h2(v0, v1);
            }
        }
    }
}

// ==================== launch (round-11 structure + fp16 mirrors) ====================
extern "C" void kernel_launch(void* const* d_in, const int* in_sizes, int n_in,
                              void* d_out, int out_size) {
    const float* x   = (const float*)d_in[0];
    const int*   ei0 = (const int*)d_in[1];
    const int*   ei1 = (const int*)d_in[2];
    const int*   ei2 = (const int*)d_in[3];
    const float* ea  = (const float*)d_in[4];
    const float* W1  = (const float*)d_in[5];
    const float* b1  = (const float*)d_in[6];
    const float* g1  = (const float*)d_in[7];
    const float* be1 = (const float*)d_in[8];
    const float* m1  = (const float*)d_in[9];
    const float* v1  = (const float*)d_in[10];
    const float* Wl2 = (const float*)d_in[11];
    const float* bl2 = (const float*)d_in[12];
    const float* Wr2 = (const float*)d_in[13];
    const float* g2  = (const float*)d_in[14];
    const float* be2 = (const float*)d_in[15];
    const float* m2  = (const float*)d_in[16];
    const float* v2  = (const float*)d_in[17];
    const float* Wl3 = (const float*)d_in[18];
    const float* bl3 = (const float*)d_in[19];
    const float* Wr3 = (const float*)d_in[20];
    const float* g3  = (const float*)d_in[21];
    const float* be3 = (const float*)d_in[22];
    const float* m3  = (const float*)d_in[23];
    const float* v3  = (const float*)d_in[24];
    const float* W4  = (const float*)d_in[25];
    const float* b4  = (const float*)d_in[26];
    const float* W5  = (const float*)d_in[27];
    const float* b5  = (const float*)d_in[28];
    float* out = (float*)d_out;

    unsigned int *a1h, *a1l, *aggh, *aggl, *h1h, *h1l, *h2h, *h2l, *h3h, *h3l;
    unsigned int *h1f, *h2f, *xf, *xh, *xl;
    float *invc;
    int *cnt, *rowptr, *cursor, *col12, *partial;
    int2* col0e;
    unsigned short *B1, *B2, *B3, *B4;
    cudaGetSymbolAddress((void**)&a1h, g_a1h);   cudaGetSymbolAddress((void**)&a1l, g_a1l);
    cudaGetSymbolAddress((void**)&aggh, g_aggh); cudaGetSymbolAddress((void**)&aggl, g_aggl);
    cudaGetSymbolAddress((void**)&h1h, g_h1h);   cudaGetSymbolAddress((void**)&h1l, g_h1l);
    cudaGetSymbolAddress((void**)&h2h, g_h2h);   cudaGetSymbolAddress((void**)&h2l, g_h2l);
    cudaGetSymbolAddress((void**)&h3h, g_h3h);   cudaGetSymbolAddress((void**)&h3l, g_h3l);
    cudaGetSymbolAddress((void**)&h1f, g_h1f);   cudaGetSymbolAddress((void**)&h2f, g_h2f);
    cudaGetSymbolAddress((void**)&xf, g_xf);
    cudaGetSymbolAddress((void**)&xh, g_xh);     cudaGetSymbolAddress((void**)&xl, g_xl);
    cudaGetSymbolAddress((void**)&cnt, g_cnt);
    cudaGetSymbolAddress((void**)&invc, g_invc);
    cudaGetSymbolAddress((void**)&rowptr, g_rowptr);
    cudaGetSymbolAddress((void**)&cursor, g_cursor);
    cudaGetSymbolAddress((void**)&partial, g_partial);
    cudaGetSymbolAddress((void**)&col0e, g_col0e);
    cudaGetSymbolAddress((void**)&col12, g_col12);
    cudaGetSymbolAddress((void**)&B1, g_B1);
    cudaGetSymbolAddress((void**)&B2, g_B2);
    cudaGetSymbolAddress((void**)&B3, g_B3);
    cudaGetSymbolAddress((void**)&B4, g_B4);

    const int SMC = 2 * (128 * 128 + 2 * 128 * 128);  // 98304
    const int SMM = 2 * (128 * 128 + 2 * 64 * 128);   // 65536
    cudaFuncSetAttribute(gemm_mma<128, 0, 128, 0>,
                         cudaFuncAttributeMaxDynamicSharedMemorySize, SMC);
    cudaFuncSetAttribute(gemm_mma<128, 128, 128, 1>,
                         cudaFuncAttributeMaxDynamicSharedMemorySize, SMC);
    cudaFuncSetAttribute(gemm_mma<128, 64, 64, 2>,
                         cudaFuncAttributeMaxDynamicSharedMemorySize, SMM);

    static cudaStream_t s1 = nullptr;
    static cudaEvent_t evRoot = nullptr, evB = nullptr;
    if (s1 == nullptr) {
        cudaStreamCreateWithFlags(&s1, cudaStreamNonBlocking);
        cudaEventCreateWithFlags(&evRoot, cudaEventDisableTiming);
        cudaEventCreateWithFlags(&evB, cudaEventDisableTiming);
    }

    const int agg_grid = (NN + 7) / 8;
    const int G = (NN + 127) / 128;  // 391
    dim3 scan0_grid(SCAN_NBLK, 1);
    dim3 scan12_grid(SCAN_NBLK, 2);

    // ---- root: zero counts, then fork ----
    cudaMemsetAsync(cnt, 0, 3 * NN * sizeof(int), 0);
    cudaEventRecord(evRoot, 0);
    cudaStreamWaitEvent(s1, evRoot, 0);

    // ---- side stream s1: lists 1,2 CSR + heavy prep ----
    count12_prep<<<(2 * EE + SX + SB2 + SB3 + SB4 + 255) / 256, 256, 0, s1>>>(
        ei1, ei2, cnt, x, xh, xl, Wl2, Wr2, Wl3, Wr3, W4, B2, B3, B4);
    scanA<<<scan12_grid, 256, 0, s1>>>(cnt, partial, 1);
    scanC<<<scan12_grid, 256, 0, s1>>>(cnt, partial, rowptr, cursor, invc, 1);
    fill12<<<(2 * EE + 255) / 256, 256, 0, s1>>>(ei1, ei2, cursor, col12);
    cudaEventRecord(evB, s1);

    // ---- critical stream 0: list0 CSR (+ x fp16 mirror) -> conv1 ----
    count0_prepB1<<<(EE + SB1 + SXF + 255) / 256, 256>>>(ei0, cnt, W1, B1, x, xf);
    scanA<<<scan0_grid, 256>>>(cnt, partial, 0);
    scanC<<<scan0_grid, 256>>>(cnt, partial, rowptr, cursor, invc, 0);
    fill0<<<(EE + 255) / 256, 256>>>(ei0, cursor, col0e);
    agg1_kernel<<<agg_grid, 256>>>(xf, ea, rowptr, col0e, invc, a1h, a1l);
    gemm_mma<128, 0, 128, 0><<<G, 256, SMC>>>(
        (unsigned short*)a1h, (unsigned short*)a1l,
        (unsigned short*)a1h, (unsigned short*)a1l,
        B1, b1, g1, be1, m1, v1, invc, h1h, h1l, h1f, nullptr, nullptr, nullptr);

    // ---- join ----
    cudaStreamWaitEvent(0, evB, 0);

    // conv2
    aggH_kernel<<<agg_grid, 256>>>(h1f, rowptr + (NN + 1), col12, invc + NN, aggh, aggl);
    gemm_mma<128, 128, 128, 1><<<G, 256, SMC>>>(
        (unsigned short*)aggh, (unsigned short*)aggl,
        (unsigned short*)h1h, (unsigned short*)h1l,
        B2, bl2, g2, be2, m2, v2, nullptr, h2h, h2l, h2f, nullptr, nullptr, nullptr);
    // conv3
    aggH_kernel<<<agg_grid, 256>>>(h2f, rowptr + 2 * (NN + 1), col12 + EE,
                                   invc + 2 * NN, aggh, aggl);
    gemm_mma<128, 128, 128, 1><<<G, 256, SMC>>>(
        (unsigned short*)aggh, (unsigned short*)aggl,
        (unsigned short*)h2h, (unsigned short*)h2l,
        B3, bl3, g3, be3, m3, v3, nullptr, h3h, h3l, nullptr, nullptr, nullptr, nullptr);
    // readout MLP + fused W5 dot
    gemm_mma<128, 64, 64, 2><<<G, 256, SMM>>>(
        (unsigned short*)h3h, (unsigned short*)h3l,
        (unsigned short*)xh, (unsigned short*)xl,
        B4, b4, nullptr, nullptr, nullptr, nullptr, nullptr,
        nullptr, nullptr, nullptr, W5, b5, out);
}